// round 11
// baseline (speedup 1.0000x reference)
#include <cuda_runtime.h>
#include <cuda_fp16.h>
#include <cstdint>

// ---------------------------------------------------------------------------
// PositionAttentionModule: B=4, HW=4096, C=512, Cr=64
//   q|k = x@[W1|W2]      3-term split HMMA (proven) -> q,k hi/lo fp16
//   v   = x@W3           f16 HMMA NT (proven) -> vT fp16
//   exp_tiles            3-term split QK^T; writes e=2^(l*log2e - m_tile) fp16
//                        + per-(row,tile) stats. NO fp32 logits in HBM.
//   reduce_stats         per-row M, Z; alpha'[row][tile] = 2^(m_t-M)/Z (fp16)
//   scale_probs          p = e * alpha'   (elementwise, normalized probs)
//   E = s @ v            f16 HMMA NT (proven), fused gamma*E + x
// Rule R7: device globals referenced ONLY inside kernel bodies.
// ---------------------------------------------------------------------------

constexpr int kHW  = 4096;
constexpr int kC   = 512;
constexpr int kTok = 4 * kHW;   // 16384

__device__ __half g_qs  [kTok * 128];                   // 4 MB q split [hi|lo]
__device__ __half g_ks  [kTok * 128];                   // 4 MB k split [hi|lo]
__device__ __half g_sh  [(size_t)4 * kHW * kHW];        // 128 MB fp16 e / probs
__device__ float  g_mt  [(size_t)kTok * 32];            // 2 MB per-(row,tile) max (base2)
__device__ float  g_st  [(size_t)kTok * 32];            // 2 MB per-(row,tile) sum
__device__ __half g_scale[(size_t)kTok * 32];           // 1 MB alpha'[row][tile]
__device__ __half g_vT  [(size_t)4 * kC * kHW];         // 16 MB vT[b][n][i]
__device__ __half g_xh  [(size_t)kTok * kC];            // 16 MB x hi fp16 [m][k]
__device__ __half g_xl  [(size_t)kTok * kC];            // 16 MB x lo fp16 [m][k]
__device__ __half g_w12h[128 * kC];                     // 128 KB W12^T hi [n][k]
__device__ __half g_w12l[128 * kC];                     // 128 KB W12^T lo [n][k]
__device__ __half g_w3T [kC * kC];                      // 512 KB W3^T fp16 [n][k]

// ============================ PTX helpers ==================================
__device__ __forceinline__ uint32_t smem_u32(const void* p) {
    uint32_t a;
    asm("{ .reg .u64 t; cvta.to.shared.u64 t, %1; cvt.u32.u64 %0, t; }"
        : "=r"(a) : "l"(p));
    return a;
}
__device__ __forceinline__ void ldmx4(uint32_t& r0, uint32_t& r1, uint32_t& r2,
                                      uint32_t& r3, uint32_t a) {
    asm volatile("ldmatrix.sync.aligned.m8n8.x4.shared.b16 {%0,%1,%2,%3}, [%4];"
                 : "=r"(r0), "=r"(r1), "=r"(r2), "=r"(r3) : "r"(a));
}
__device__ __forceinline__ void mma16816(float* c, const uint32_t* a,
                                         const uint32_t* b) {
    asm volatile(
        "mma.sync.aligned.m16n8k16.row.col.f32.f16.f16.f32 "
        "{%0,%1,%2,%3}, {%4,%5,%6,%7}, {%8,%9}, {%0,%1,%2,%3};"
        : "+f"(c[0]), "+f"(c[1]), "+f"(c[2]), "+f"(c[3])
        : "r"(a[0]), "r"(a[1]), "r"(a[2]), "r"(a[3]), "r"(b[0]), "r"(b[1]));
}
#define CP16(sm, gp) \
    asm volatile("cp.async.cg.shared.global [%0], [%1], 16;" :: "r"(sm), "l"(gp))
#define CP_COMMIT() asm volatile("cp.async.commit_group;" ::: "memory")
#define CP_WAIT(n)  asm volatile("cp.async.wait_group %0;" :: "n"(n) : "memory")

// exp2 on the FMA pipe (degree-7, rel err ~2e-7)
__device__ __forceinline__ float exp2f_fast(float f) {
    f = fmaxf(f, -126.f);
    float n = floorf(f);
    float r = f - n;
    float p = 1.5252734e-5f;
    p = fmaf(p, r, 1.5403530e-4f);
    p = fmaf(p, r, 1.3333558e-3f);
    p = fmaf(p, r, 9.6181291e-3f);
    p = fmaf(p, r, 5.5504109e-2f);
    p = fmaf(p, r, 2.4022651e-1f);
    p = fmaf(p, r, 6.9314718e-1f);
    p = fmaf(p, r, 1.0f);
    return p * __int_as_float((((int)n) + 127) << 23);
}
constexpr float LOG2E = 1.4426950408889634f;

// ---------------------------------------------------------------------------
__global__ __launch_bounds__(256) void concat_w_split(const float* __restrict__ W1,
                                                      const float* __restrict__ W2) {
    int idx = blockIdx.x * 256 + threadIdx.x;           // < 65536
    int n = idx >> 9, k = idx & 511;
    float v = (n < 64) ? W1[k * 64 + n] : W2[k * 64 + (n - 64)];
    __half hi = __float2half_rn(v);
    __half lo = __float2half_rn(v - __half2float(hi));
    g_w12h[idx] = hi;
    g_w12l[idx] = lo;
}

__global__ __launch_bounds__(256) void to_half_x(const float* __restrict__ x) {
    int idx = blockIdx.x * 256 + threadIdx.x;
    float4 v = *(const float4*)(x + (size_t)idx * 4);
    __half h0 = __float2half_rn(v.x), h1 = __float2half_rn(v.y);
    __half h2 = __float2half_rn(v.z), h3 = __float2half_rn(v.w);
    __half2* dh = (__half2*)(g_xh + (size_t)idx * 4);
    dh[0] = __halves2half2(h0, h1);
    dh[1] = __halves2half2(h2, h3);
    __half2* dl = (__half2*)(g_xl + (size_t)idx * 4);
    dl[0] = __floats2half2_rn(v.x - __half2float(h0), v.y - __half2float(h1));
    dl[1] = __floats2half2_rn(v.z - __half2float(h2), v.w - __half2float(h3));
}

__global__ __launch_bounds__(256) void transpose_w3(const float* __restrict__ W3) {
    __shared__ float t[32][33];
    const int tx = threadIdx.x & 31, ty = threadIdx.x >> 5;
    const int n0 = blockIdx.x * 32;
    const int k0 = blockIdx.y * 32;
    #pragma unroll
    for (int j = 0; j < 4; j++) {
        int kk = ty + j * 8;
        t[kk][tx] = W3[(size_t)(k0 + kk) * kC + n0 + tx];
    }
    __syncthreads();
    #pragma unroll
    for (int j = 0; j < 4; j++) {
        int nn = ty + j * 8;
        g_w3T[(size_t)(n0 + nn) * kC + k0 + tx] = __float2half_rn(t[tx][nn]);
    }
}

// ============ HMMA NT skeleton constants ===================================
constexpr int PV_LDA  = 72;                         // halves, padded
constexpr int PV_ABUF = 128 * PV_LDA * 2;           // 18432 B
constexpr int PV_SMEM = 4 * PV_ABUF;                // 73728 B

// ====================== HMMA: PV (E = s @ v), fused epilogue (proven) ======
__global__ void __launch_bounds__(256, 2)
pv_mma(const float* __restrict__ x, const float* __restrict__ gamma,
       float* __restrict__ out) {
    extern __shared__ char smem[];
    const uint32_t sb  = smem_u32(smem);
    const int tid  = threadIdx.x;
    const int lane = tid & 31, wid = tid >> 5;
    const int wm = (wid & 1) * 64, wn = (wid >> 1) * 32;
    const int n0 = blockIdx.x * 128, m0 = blockIdx.y * 128, bz = blockIdx.z;

    const __half* Asrc = g_sh + (size_t)bz * kHW * kHW + (size_t)m0 * kHW;
    const __half* Bsrc = g_vT + (size_t)bz * kC * kHW + (size_t)n0 * kHW;

    const uint32_t sA[2] = {sb, sb + PV_ABUF};
    const uint32_t sB[2] = {sb + 2 * PV_ABUF, sb + 3 * PV_ABUF};

    const int ldrow  = tid >> 3;
    const int ldslot = (tid & 7) * 8;

    float acc[4][4][4];
    #pragma unroll
    for (int i = 0; i < 4; i++)
        #pragma unroll
        for (int j = 0; j < 4; j++)
            #pragma unroll
            for (int r = 0; r < 4; r++) acc[i][j][r] = 0.f;

    const int aRow = wm + (lane & 15);
    const int aCol = (lane >> 4) * 8;
    const int bRow = wn + ((lane >> 4) << 3) + (lane & 7);
    const int bCol = ((lane >> 3) & 1) * 8;

    #pragma unroll
    for (int q = 0; q < 4; q++) {
        int r = q * 32 + ldrow;
        CP16(sA[0] + (r * PV_LDA + ldslot) * 2, Asrc + (size_t)r * kHW + ldslot);
        CP16(sB[0] + (r * PV_LDA + ldslot) * 2, Bsrc + (size_t)r * kHW + ldslot);
    }
    CP_COMMIT();

    for (int i = 0; i < 64; i++) {
        const int buf = i & 1;
        if (i < 63) {
            const int k0 = (i + 1) * 64;
            #pragma unroll
            for (int q = 0; q < 4; q++) {
                int r = q * 32 + ldrow;
                CP16(sA[buf ^ 1] + (r * PV_LDA + ldslot) * 2,
                     Asrc + (size_t)r * kHW + k0 + ldslot);
                CP16(sB[buf ^ 1] + (r * PV_LDA + ldslot) * 2,
                     Bsrc + (size_t)r * kHW + k0 + ldslot);
            }
            CP_COMMIT();
            CP_WAIT(1);
        } else {
            CP_WAIT(0);
        }
        __syncthreads();

        #pragma unroll
        for (int ks = 0; ks < 4; ks++) {
            uint32_t af[4][4], bf[4][2];
            #pragma unroll
            for (int mt = 0; mt < 4; mt++)
                ldmx4(af[mt][0], af[mt][1], af[mt][2], af[mt][3],
                      sA[buf] + ((aRow + mt * 16) * PV_LDA + aCol + ks * 16) * 2);
            #pragma unroll
            for (int np = 0; np < 2; np++)
                ldmx4(bf[np * 2][0], bf[np * 2][1], bf[np * 2 + 1][0], bf[np * 2 + 1][1],
                      sB[buf] + ((bRow + np * 16) * PV_LDA + bCol + ks * 16) * 2);
            #pragma unroll
            for (int mt = 0; mt < 4; mt++)
                #pragma unroll
                for (int nt = 0; nt < 4; nt++)
                    mma16816(acc[mt][nt], af[mt], bf[nt]);
        }
        __syncthreads();
    }

    float* stage = (float*)smem;          // [128][132] as [n][m]
    #pragma unroll
    for (int mt = 0; mt < 4; mt++)
        #pragma unroll
        for (int nt = 0; nt < 4; nt++)
            #pragma unroll
            for (int r = 0; r < 4; r++) {
                int m = wm + mt * 16 + (lane >> 2) + ((r >= 2) ? 8 : 0);
                int n = wn + nt * 8 + (lane & 3) * 2 + (r & 1);
                stage[n * 132 + m] = acc[mt][nt][r];
            }
    __syncthreads();

    const float g = __ldg(gamma);
    const size_t obofs = (size_t)bz * kHW * kC;
    #pragma unroll
    for (int q = 0; q < 16; q++) {
        int idx = tid + q * 256;
        int n   = idx >> 5;
        int m4  = (idx & 31) << 2;
        size_t o = obofs + (size_t)(n0 + n) * kHW + m0 + m4;
        float4 xv = *(const float4*)(x + o);
        const float* sp = stage + n * 132 + m4;
        *(float4*)(out + o) = make_float4(fmaf(g, sp[0], xv.x), fmaf(g, sp[1], xv.y),
                                          fmaf(g, sp[2], xv.z), fmaf(g, sp[3], xv.w));
    }
}

// ============ HMMA: V-proj NT (proven): vT = (x @ W3)^T ====================
__global__ void __launch_bounds__(256, 2) vproj_mma() {
    extern __shared__ char smem[];
    const uint32_t sb  = smem_u32(smem);
    const int tid  = threadIdx.x;
    const int lane = tid & 31, wid = tid >> 5;
    const int wm = (wid & 1) * 64, wn = (wid >> 1) * 32;
    const int n0 = blockIdx.x * 128, m0 = blockIdx.y * 128;

    const __half* Asrc = g_xh + (size_t)m0 * kC;
    const __half* Bsrc = g_w3T + (size_t)n0 * kC;

    const uint32_t sA[2] = {sb, sb + PV_ABUF};
    const uint32_t sB[2] = {sb + 2 * PV_ABUF, sb + 3 * PV_ABUF};

    const int ldrow  = tid >> 3;
    const int ldslot = (tid & 7) * 8;

    float acc[4][4][4];
    #pragma unroll
    for (int i = 0; i < 4; i++)
        #pragma unroll
        for (int j = 0; j < 4; j++)
            #pragma unroll
            for (int r = 0; r < 4; r++) acc[i][j][r] = 0.f;

    const int aRow = wm + (lane & 15);
    const int aCol = (lane >> 4) * 8;
    const int bRow = wn + ((lane >> 4) << 3) + (lane & 7);
    const int bCol = ((lane >> 3) & 1) * 8;

    #pragma unroll
    for (int q = 0; q < 4; q++) {
        int r = q * 32 + ldrow;
        CP16(sA[0] + (r * PV_LDA + ldslot) * 2, Asrc + (size_t)r * kC + ldslot);
        CP16(sB[0] + (r * PV_LDA + ldslot) * 2, Bsrc + (size_t)r * kC + ldslot);
    }
    CP_COMMIT();

    for (int i = 0; i < 8; i++) {
        const int buf = i & 1;
        if (i < 7) {
            const int k0 = (i + 1) * 64;
            #pragma unroll
            for (int q = 0; q < 4; q++) {
                int r = q * 32 + ldrow;
                CP16(sA[buf ^ 1] + (r * PV_LDA + ldslot) * 2,
                     Asrc + (size_t)r * kC + k0 + ldslot);
                CP16(sB[buf ^ 1] + (r * PV_LDA + ldslot) * 2,
                     Bsrc + (size_t)r * kC + k0 + ldslot);
            }
            CP_COMMIT();
            CP_WAIT(1);
        } else {
            CP_WAIT(0);
        }
        __syncthreads();

        #pragma unroll
        for (int ks = 0; ks < 4; ks++) {
            uint32_t af[4][4], bf[4][2];
            #pragma unroll
            for (int mt = 0; mt < 4; mt++)
                ldmx4(af[mt][0], af[mt][1], af[mt][2], af[mt][3],
                      sA[buf] + ((aRow + mt * 16) * PV_LDA + aCol + ks * 16) * 2);
            #pragma unroll
            for (int np = 0; np < 2; np++)
                ldmx4(bf[np * 2][0], bf[np * 2][1], bf[np * 2 + 1][0], bf[np * 2 + 1][1],
                      sB[buf] + ((bRow + np * 16) * PV_LDA + bCol + ks * 16) * 2);
            #pragma unroll
            for (int mt = 0; mt < 4; mt++)
                #pragma unroll
                for (int nt = 0; nt < 4; nt++)
                    mma16816(acc[mt][nt], af[mt], bf[nt]);
        }
        __syncthreads();
    }

    __half* stage = (__half*)smem;        // [128][136]
    constexpr int SLD = 136;
    #pragma unroll
    for (int mt = 0; mt < 4; mt++)
        #pragma unroll
        for (int nt = 0; nt < 4; nt++)
            #pragma unroll
            for (int r = 0; r < 4; r++) {
                int m = wm + mt * 16 + (lane >> 2) + ((r >= 2) ? 8 : 0);
                int n = wn + nt * 8 + (lane & 3) * 2 + (r & 1);
                stage[n * SLD + m] = __float2half_rn(acc[mt][nt][r]);
            }
    __syncthreads();

    const int bz = m0 >> 12;
    const int ml = m0 & 4095;
    #pragma unroll
    for (int q = 0; q < 8; q++) {
        int idx = tid + q * 256;
        int n   = idx >> 4;
        int m8  = (idx & 15) << 3;
        __half* dst = g_vT + ((size_t)bz * kC + n0 + n) * kHW + ml + m8;
        *(uint4*)dst = *(uint4*)(stage + n * SLD + m8);
    }
}

// ===== HMMA: q|k projection via 3-term split (proven), emits hi/lo =========
__global__ void __launch_bounds__(256, 2) qkproj_mma() {
    extern __shared__ char smem[];
    const uint32_t sb  = smem_u32(smem);
    const int tid  = threadIdx.x;
    const int lane = tid & 31, wid = tid >> 5;
    const int wm = (wid & 1) * 64, wn = (wid >> 1) * 32;
    const int m0 = blockIdx.y * 128;

    const uint32_t sA[2] = {sb, sb + PV_ABUF};
    const uint32_t sB[2] = {sb + 2 * PV_ABUF, sb + 3 * PV_ABUF};

    const int ldrow  = tid >> 3;
    const int ldslot = (tid & 7) * 8;

    float acc[4][4][4];
    #pragma unroll
    for (int i = 0; i < 4; i++)
        #pragma unroll
        for (int j = 0; j < 4; j++)
            #pragma unroll
            for (int r = 0; r < 4; r++) acc[i][j][r] = 0.f;

    const int aRow = wm + (lane & 15);
    const int aCol = (lane >> 4) * 8;
    const int bRow = wn + ((lane >> 4) << 3) + (lane & 7);
    const int bCol = ((lane >> 3) & 1) * 8;

#define QK_PREFETCH(i, buf) do {                                               \
    const int term = (i) >> 3, kc = (i) & 7;                                   \
    const __half* Ap = ((term == 1) ? g_xl : g_xh) + (size_t)m0 * kC + kc * 64; \
    const __half* Bp = ((term == 2) ? g_w12l : g_w12h) + kc * 64;              \
    _Pragma("unroll") for (int q = 0; q < 4; q++) {                            \
        int r = q * 32 + ldrow;                                                \
        CP16(sA[buf] + (r * PV_LDA + ldslot) * 2, Ap + (size_t)r * kC + ldslot); \
        CP16(sB[buf] + (r * PV_LDA + ldslot) * 2, Bp + (size_t)r * kC + ldslot); \
    }                                                                          \
    CP_COMMIT();                                                               \
} while (0)

    QK_PREFETCH(0, 0);
    for (int i = 0; i < 24; i++) {
        const int buf = i & 1;
        if (i < 23) { QK_PREFETCH(i + 1, buf ^ 1); CP_WAIT(1); }
        else        { CP_WAIT(0); }
        __syncthreads();

        #pragma unroll
        for (int ks = 0; ks < 4; ks++) {
            uint32_t af[4][4], bf[4][2];
            #pragma unroll
            for (int mt = 0; mt < 4; mt++)
                ldmx4(af[mt][0], af[mt][1], af[mt][2], af[mt][3],
                      sA[buf] + ((aRow + mt * 16) * PV_LDA + aCol + ks * 16) * 2);
            #pragma unroll
            for (int np = 0; np < 2; np++)
                ldmx4(bf[np * 2][0], bf[np * 2][1], bf[np * 2 + 1][0], bf[np * 2 + 1][1],
                      sB[buf] + ((bRow + np * 16) * PV_LDA + bCol + ks * 16) * 2);
            #pragma unroll
            for (int mt = 0; mt < 4; mt++)
                #pragma unroll
                for (int nt = 0; nt < 4; nt++)
                    mma16816(acc[mt][nt], af[mt], bf[nt]);
        }
        __syncthreads();
    }
#undef QK_PREFETCH

    float* stage = (float*)smem;          // [128][132]
    #pragma unroll
    for (int mt = 0; mt < 4; mt++)
        #pragma unroll
        for (int nt = 0; nt < 4; nt++)
            #pragma unroll
            for (int r = 0; r < 4; r++) {
                int m = wm + mt * 16 + (lane >> 2) + ((r >= 2) ? 8 : 0);
                int n = wn + nt * 8 + (lane & 3) * 2 + (r & 1);
                stage[m * 132 + n] = acc[mt][nt][r];
            }
    __syncthreads();

    #pragma unroll
    for (int q = 0; q < 16; q++) {
        int idx = tid + q * 256;
        int t   = idx >> 5;
        int c4  = (idx & 31) << 2;
        const float* sp = stage + t * 132 + c4;
        __half hi[4], lo[4];
        #pragma unroll
        for (int j = 0; j < 4; j++) {
            hi[j] = __float2half_rn(sp[j]);
            lo[j] = __float2half_rn(sp[j] - __half2float(hi[j]));
        }
        __half* base = (c4 < 64) ? (g_qs + (size_t)(m0 + t) * 128 + c4)
                                 : (g_ks + (size_t)(m0 + t) * 128 + (c4 - 64));
        *(uint2*)base        = *(uint2*)hi;
        *(uint2*)(base + 64) = *(uint2*)lo;
    }
}

// ========== HMMA: exp tiles = QK^T (3-term split) + tile-local exp =========
// Writes e = 2^(l*log2e - m_tile) fp16 to g_sh; (m_tile, s_tile) to g_mt/g_st.
__global__ void __launch_bounds__(256, 2) exp_tiles() {
    extern __shared__ char smem[];
    const uint32_t sb  = smem_u32(smem);
    const int tid  = threadIdx.x;
    const int lane = tid & 31, wid = tid >> 5;
    const int wm = (wid & 1) * 64, wn = (wid >> 1) * 32;
    const int n0 = blockIdx.x * 128, m0 = blockIdx.y * 128, bz = blockIdx.z;

    const __half* Asrc = g_qs + ((size_t)bz * kHW + m0) * 128;
    const __half* Bsrc = g_ks + ((size_t)bz * kHW + n0) * 128;

    const uint32_t sA[2] = {sb, sb + PV_ABUF};
    const uint32_t sB[2] = {sb + 2 * PV_ABUF, sb + 3 * PV_ABUF};

    const int ldrow  = tid >> 3;
    const int ldslot = (tid & 7) * 8;

    float acc[4][4][4];
    #pragma unroll
    for (int i = 0; i < 4; i++)
        #pragma unroll
        for (int j = 0; j < 4; j++)
            #pragma unroll
            for (int r = 0; r < 4; r++) acc[i][j][r] = 0.f;

    const int aRow = wm + (lane & 15);
    const int aCol = (lane >> 4) * 8;
    const int bRow = wn + ((lane >> 4) << 3) + (lane & 7);
    const int bCol = ((lane >> 3) & 1) * 8;

    const int AOFF[3] = {0, 64, 0};
    const int BOFF[3] = {0, 0, 64};

    #pragma unroll
    for (int q = 0; q < 4; q++) {
        int r = q * 32 + ldrow;
        CP16(sA[0] + (r * PV_LDA + ldslot) * 2, Asrc + (size_t)r * 128 + AOFF[0] + ldslot);
        CP16(sB[0] + (r * PV_LDA + ldslot) * 2, Bsrc + (size_t)r * 128 + BOFF[0] + ldslot);
    }
    CP_COMMIT();

    for (int i = 0; i < 3; i++) {
        const int buf = i & 1;
        if (i < 2) {
            #pragma unroll
            for (int q = 0; q < 4; q++) {
                int r = q * 32 + ldrow;
                CP16(sA[buf ^ 1] + (r * PV_LDA + ldslot) * 2,
                     Asrc + (size_t)r * 128 + AOFF[i + 1] + ldslot);
                CP16(sB[buf ^ 1] + (r * PV_LDA + ldslot) * 2,
                     Bsrc + (size_t)r * 128 + BOFF[i + 1] + ldslot);
            }
            CP_COMMIT();
            CP_WAIT(1);
        } else {
            CP_WAIT(0);
        }
        __syncthreads();

        #pragma unroll
        for (int ks = 0; ks < 4; ks++) {
            uint32_t af[4][4], bf[4][2];
            #pragma unroll
            for (int mt = 0; mt < 4; mt++)
                ldmx4(af[mt][0], af[mt][1], af[mt][2], af[mt][3],
                      sA[buf] + ((aRow + mt * 16) * PV_LDA + aCol + ks * 16) * 2);
            #pragma unroll
            for (int np = 0; np < 2; np++)
                ldmx4(bf[np * 2][0], bf[np * 2][1], bf[np * 2 + 1][0], bf[np * 2 + 1][1],
                      sB[buf] + ((bRow + np * 16) * PV_LDA + bCol + ks * 16) * 2);
            #pragma unroll
            for (int mt = 0; mt < 4; mt++)
                #pragma unroll
                for (int nt = 0; nt < 4; nt++)
                    mma16816(acc[mt][nt], af[mt], bf[nt]);
        }
        __syncthreads();
    }

    // stage [m][n] fp32
    float* stage = (float*)smem;                     // [128][132] = 67584 B
    float* sm_m2 = (float*)(smem + 128 * 132 * 4);   // [128] row base-2 max
    #pragma unroll
    for (int mt = 0; mt < 4; mt++)
        #pragma unroll
        for (int nt = 0; nt < 4; nt++)
            #pragma unroll
            for (int r = 0; r < 4; r++) {
                int m = wm + mt * 16 + (lane >> 2) + ((r >= 2) ? 8 : 0);
                int n = wn + nt * 8 + (lane & 3) * 2 + (r & 1);
                stage[m * 132 + n] = acc[mt][nt][r];
            }
    __syncthreads();

    // per-row tile stats: 2 threads per row over 64 cols each
    {
        const int row = tid >> 1, h = tid & 1;
        const float* rp = stage + row * 132 + h * 64;
        float mx = -1e30f;
        #pragma unroll
        for (int c = 0; c < 64; c++) mx = fmaxf(mx, rp[c]);
        mx = fmaxf(mx, __shfl_xor_sync(0xffffffffu, mx, 1));
        float m2 = mx * LOG2E;
        float s = 0.f;
        #pragma unroll
        for (int c = 0; c < 64; c++) s += exp2f_fast(fmaf(rp[c], LOG2E, -m2));
        s += __shfl_xor_sync(0xffffffffu, s, 1);
        if (h == 0) {
            sm_m2[row] = m2;
            size_t ridx = ((size_t)bz * kHW + m0 + row) * 32 + (n0 >> 7);
            g_mt[ridx] = m2;
            g_st[ridx] = s;
        }
    }
    __syncthreads();

    // write e = 2^(l*log2e - m2_row) fp16
    __half* Pp = g_sh + (size_t)bz * kHW * kHW;
    #pragma unroll
    for (int q = 0; q < 16; q++) {
        int idx = tid + q * 256;
        int m   = idx >> 5;
        int n4  = (idx & 31) << 2;
        const float* sp = stage + m * 132 + n4;
        const float m2r = sm_m2[m];
        __half2 h0 = __floats2half2_rn(exp2f_fast(fmaf(sp[0], LOG2E, -m2r)),
                                       exp2f_fast(fmaf(sp[1], LOG2E, -m2r)));
        __half2 h1 = __floats2half2_rn(exp2f_fast(fmaf(sp[2], LOG2E, -m2r)),
                                       exp2f_fast(fmaf(sp[3], LOG2E, -m2r)));
        uint2 u;
        u.x = *reinterpret_cast<uint32_t*>(&h0);
        u.y = *reinterpret_cast<uint32_t*>(&h1);
        *(uint2*)(Pp + (size_t)(m0 + m) * kHW + n0 + n4) = u;
    }
}

// ===== per-row reduce: M = max m2_t, Z = sum s_t*2^(m2_t-M), alpha' fp16 ====
__global__ __launch_bounds__(256) void reduce_stats() {
    const int row  = blockIdx.x * 8 + (threadIdx.x >> 5);   // 16384 rows
    const int lane = threadIdx.x & 31;
    const size_t base = (size_t)row * 32;
    float m2 = g_mt[base + lane];
    float s  = g_st[base + lane];
    float M2 = m2;
    #pragma unroll
    for (int o = 16; o > 0; o >>= 1) M2 = fmaxf(M2, __shfl_xor_sync(0xffffffffu, M2, o));
    float a = exp2f_fast(m2 - M2);
    float z = s * a;
    #pragma unroll
    for (int o = 16; o > 0; o >>= 1) z += __shfl_xor_sync(0xffffffffu, z, o);
    g_scale[base + lane] = __float2half_rn(a / z);
}

// ===== scale probs: p = e * alpha'[row][tile]  (uint4 elementwise) =========
__global__ __launch_bounds__(256) void scale_probs() {
    size_t idx = (size_t)blockIdx.x * 256 + threadIdx.x;    // uint4 idx, 8388608
    uint4 v = *((const uint4*)g_sh + idx);
    int row  = (int)(idx >> 9);          // 512 uint4 per 4096-wide row
    int tile = (int)((idx >> 4) & 31);   // 16 uint4 per 128-wide tile
    __half2 a2 = __half2half2(g_scale[(size_t)row * 32 + tile]);
    __half2* h = (__half2*)&v;
    h[0] = __hmul2(h[0], a2);
    h[1] = __hmul2(h[1], a2);
    h[2] = __hmul2(h[2], a2);
    h[3] = __hmul2(h[3], a2);
    *((uint4*)g_sh + idx) = v;
}

// ---------------------------------------------------------------------------
extern "C" void kernel_launch(void* const* d_in, const int* in_sizes, int n_in,
                              void* d_out, int out_size) {
    const float* x     = (const float*)d_in[0];
    const float* W1    = (const float*)d_in[1];
    const float* W2    = (const float*)d_in[2];
    const float* W3    = (const float*)d_in[3];
    const float* gamma = (const float*)d_in[4];
    float* out = (float*)d_out;

    cudaFuncSetAttribute(pv_mma, cudaFuncAttributeMaxDynamicSharedMemorySize, PV_SMEM);
    cudaFuncSetAttribute(vproj_mma, cudaFuncAttributeMaxDynamicSharedMemorySize, PV_SMEM);
    cudaFuncSetAttribute(qkproj_mma, cudaFuncAttributeMaxDynamicSharedMemorySize, PV_SMEM);
    cudaFuncSetAttribute(exp_tiles, cudaFuncAttributeMaxDynamicSharedMemorySize, PV_SMEM);

    concat_w_split<<<256, 256>>>(W1, W2);                 // W12^T hi/lo
    to_half_x<<<8192, 256>>>(x);                          // x hi/lo fp16
    transpose_w3<<<dim3(16, 16), 256>>>(W3);              // W3^T fp16
    qkproj_mma<<<dim3(1, 128), 256, PV_SMEM>>>();         // q,k hi/lo (proven)
    vproj_mma<<<dim3(4, 128), 256, PV_SMEM>>>();          // vT fp16 (proven)
    exp_tiles<<<dim3(32, 32, 4), 256, PV_SMEM>>>();       // e tiles + stats
    reduce_stats<<<2048, 256>>>();                        // M, Z, alpha'
    scale_probs<<<32768, 256>>>();                        // normalize probs
    pv_mma<<<dim3(4, 32, 4), 256, PV_SMEM>>>(x, gamma, out);
}

// round 12
// speedup vs baseline: 1.1212x; 1.1212x over previous
#include <cuda_runtime.h>
#include <cuda_fp16.h>
#include <cstdint>

// ---------------------------------------------------------------------------
// PositionAttentionModule: B=4, HW=4096, C=512, Cr=64
//   q|k = x@[W1|W2]      3-term split HMMA (proven) -> q,k hi/lo fp16
//   v   = x@W3           f16 HMMA NT (proven) -> vT fp16
//   exp_tiles v2         3-term split QK^T; register-resident tile softmax
//                        stats; writes e=2^(l*log2e - m_tile) fp16 + stats
//   reduce_stats         per-row M, Z; alpha'[row][tile] = 2^(m_t-M)/Z (fp16)
//   pv_mma v2            E = (e*alpha') @ v with alpha' applied in-mainloop
//                        (hmul2 on A fragments), fused gamma*E + x epilogue
// Rule R7: device globals referenced ONLY inside kernel bodies.
// R11 lesson: alpha' factorization numerics PROVEN; execution must avoid
//   extra HBM passes and serial smem scans.
// ---------------------------------------------------------------------------

constexpr int kHW  = 4096;
constexpr int kC   = 512;
constexpr int kTok = 4 * kHW;   // 16384

__device__ __half g_qs  [kTok * 128];                   // 4 MB q split [hi|lo]
__device__ __half g_ks  [kTok * 128];                   // 4 MB k split [hi|lo]
__device__ __half g_sh  [(size_t)4 * kHW * kHW];        // 128 MB fp16 e-values
__device__ float  g_mt  [(size_t)kTok * 32];            // 2 MB per-(row,tile) max (base2)
__device__ float  g_st  [(size_t)kTok * 32];            // 2 MB per-(row,tile) sum
__device__ __half g_scale[(size_t)kTok * 32];           // 1 MB alpha'[row][tile]
__device__ __half g_vT  [(size_t)4 * kC * kHW];         // 16 MB vT[b][n][i]
__device__ __half g_xh  [(size_t)kTok * kC];            // 16 MB x hi fp16 [m][k]
__device__ __half g_xl  [(size_t)kTok * kC];            // 16 MB x lo fp16 [m][k]
__device__ __half g_w12h[128 * kC];                     // 128 KB W12^T hi [n][k]
__device__ __half g_w12l[128 * kC];                     // 128 KB W12^T lo [n][k]
__device__ __half g_w3T [kC * kC];                      // 512 KB W3^T fp16 [n][k]

// ============================ PTX helpers ==================================
__device__ __forceinline__ uint32_t smem_u32(const void* p) {
    uint32_t a;
    asm("{ .reg .u64 t; cvta.to.shared.u64 t, %1; cvt.u32.u64 %0, t; }"
        : "=r"(a) : "l"(p));
    return a;
}
__device__ __forceinline__ void ldmx4(uint32_t& r0, uint32_t& r1, uint32_t& r2,
                                      uint32_t& r3, uint32_t a) {
    asm volatile("ldmatrix.sync.aligned.m8n8.x4.shared.b16 {%0,%1,%2,%3}, [%4];"
                 : "=r"(r0), "=r"(r1), "=r"(r2), "=r"(r3) : "r"(a));
}
__device__ __forceinline__ void mma16816(float* c, const uint32_t* a,
                                         const uint32_t* b) {
    asm volatile(
        "mma.sync.aligned.m16n8k16.row.col.f32.f16.f16.f32 "
        "{%0,%1,%2,%3}, {%4,%5,%6,%7}, {%8,%9}, {%0,%1,%2,%3};"
        : "+f"(c[0]), "+f"(c[1]), "+f"(c[2]), "+f"(c[3])
        : "r"(a[0]), "r"(a[1]), "r"(a[2]), "r"(a[3]), "r"(b[0]), "r"(b[1]));
}
#define CP16(sm, gp) \
    asm volatile("cp.async.cg.shared.global [%0], [%1], 16;" :: "r"(sm), "l"(gp))
#define CP_COMMIT() asm volatile("cp.async.commit_group;" ::: "memory")
#define CP_WAIT(n)  asm volatile("cp.async.wait_group %0;" :: "n"(n) : "memory")

// exp2 on the FMA pipe (degree-7, rel err ~2e-7)
__device__ __forceinline__ float exp2f_fast(float f) {
    f = fmaxf(f, -126.f);
    float n = floorf(f);
    float r = f - n;
    float p = 1.5252734e-5f;
    p = fmaf(p, r, 1.5403530e-4f);
    p = fmaf(p, r, 1.3333558e-3f);
    p = fmaf(p, r, 9.6181291e-3f);
    p = fmaf(p, r, 5.5504109e-2f);
    p = fmaf(p, r, 2.4022651e-1f);
    p = fmaf(p, r, 6.9314718e-1f);
    p = fmaf(p, r, 1.0f);
    return p * __int_as_float((((int)n) + 127) << 23);
}
constexpr float LOG2E = 1.4426950408889634f;

// ---------------------------------------------------------------------------
__global__ __launch_bounds__(256) void concat_w_split(const float* __restrict__ W1,
                                                      const float* __restrict__ W2) {
    int idx = blockIdx.x * 256 + threadIdx.x;           // < 65536
    int n = idx >> 9, k = idx & 511;
    float v = (n < 64) ? W1[k * 64 + n] : W2[k * 64 + (n - 64)];
    __half hi = __float2half_rn(v);
    __half lo = __float2half_rn(v - __half2float(hi));
    g_w12h[idx] = hi;
    g_w12l[idx] = lo;
}

__global__ __launch_bounds__(256) void to_half_x(const float* __restrict__ x) {
    int idx = blockIdx.x * 256 + threadIdx.x;
    float4 v = *(const float4*)(x + (size_t)idx * 4);
    __half h0 = __float2half_rn(v.x), h1 = __float2half_rn(v.y);
    __half h2 = __float2half_rn(v.z), h3 = __float2half_rn(v.w);
    __half2* dh = (__half2*)(g_xh + (size_t)idx * 4);
    dh[0] = __halves2half2(h0, h1);
    dh[1] = __halves2half2(h2, h3);
    __half2* dl = (__half2*)(g_xl + (size_t)idx * 4);
    dl[0] = __floats2half2_rn(v.x - __half2float(h0), v.y - __half2float(h1));
    dl[1] = __floats2half2_rn(v.z - __half2float(h2), v.w - __half2float(h3));
}

__global__ __launch_bounds__(256) void transpose_w3(const float* __restrict__ W3) {
    __shared__ float t[32][33];
    const int tx = threadIdx.x & 31, ty = threadIdx.x >> 5;
    const int n0 = blockIdx.x * 32;
    const int k0 = blockIdx.y * 32;
    #pragma unroll
    for (int j = 0; j < 4; j++) {
        int kk = ty + j * 8;
        t[kk][tx] = W3[(size_t)(k0 + kk) * kC + n0 + tx];
    }
    __syncthreads();
    #pragma unroll
    for (int j = 0; j < 4; j++) {
        int nn = ty + j * 8;
        g_w3T[(size_t)(n0 + nn) * kC + k0 + tx] = __float2half_rn(t[tx][nn]);
    }
}

// ============ HMMA NT skeleton constants ===================================
constexpr int PV_LDA   = 72;                        // halves, padded
constexpr int PV_ABUF  = 128 * PV_LDA * 2;          // 18432 B
constexpr int PV_SMEM  = 4 * PV_ABUF;               // 73728 B
constexpr int PV2_SMEM = PV_SMEM + 128 * 33 * 4;    // + alpha_s = 90624 B

// ========= pv_mma v2: E = (e*alpha') @ v, alpha' applied in mainloop =======
__global__ void __launch_bounds__(256, 2)
pv_mma(const float* __restrict__ x, const float* __restrict__ gamma,
       float* __restrict__ out) {
    extern __shared__ char smem[];
    const uint32_t sb  = smem_u32(smem);
    const int tid  = threadIdx.x;
    const int lane = tid & 31, wid = tid >> 5;
    const int wm = (wid & 1) * 64, wn = (wid >> 1) * 32;
    const int n0 = blockIdx.x * 128, m0 = blockIdx.y * 128, bz = blockIdx.z;

    const __half* Asrc = g_sh + (size_t)bz * kHW * kHW + (size_t)m0 * kHW;
    const __half* Bsrc = g_vT + (size_t)bz * kC * kHW + (size_t)n0 * kHW;

    const uint32_t sA[2] = {sb, sb + PV_ABUF};
    const uint32_t sB[2] = {sb + 2 * PV_ABUF, sb + 3 * PV_ABUF};
    float* alpha_s = (float*)(smem + 4 * PV_ABUF);   // [128][33]

    const int ldrow  = tid >> 3;
    const int ldslot = (tid & 7) * 8;

    // load alpha'[m0+r][t] -> smem (fp32, conflict-free stride 33)
    #pragma unroll
    for (int q = 0; q < 16; q++) {
        int idx = tid + q * 256;          // 0..4095
        int r = idx >> 5, t = idx & 31;
        alpha_s[r * 33 + t] =
            __half2float(g_scale[((size_t)bz * kHW + m0 + r) * 32 + t]);
    }

    float acc[4][4][4];
    #pragma unroll
    for (int i = 0; i < 4; i++)
        #pragma unroll
        for (int j = 0; j < 4; j++)
            #pragma unroll
            for (int r = 0; r < 4; r++) acc[i][j][r] = 0.f;

    const int aRow = wm + (lane & 15);
    const int aCol = (lane >> 4) * 8;
    const int bRow = wn + ((lane >> 4) << 3) + (lane & 7);
    const int bCol = ((lane >> 3) & 1) * 8;

    #pragma unroll
    for (int q = 0; q < 4; q++) {
        int r = q * 32 + ldrow;
        CP16(sA[0] + (r * PV_LDA + ldslot) * 2, Asrc + (size_t)r * kHW + ldslot);
        CP16(sB[0] + (r * PV_LDA + ldslot) * 2, Bsrc + (size_t)r * kHW + ldslot);
    }
    CP_COMMIT();

    for (int i = 0; i < 64; i++) {
        const int buf = i & 1;
        if (i < 63) {
            const int k0 = (i + 1) * 64;
            #pragma unroll
            for (int q = 0; q < 4; q++) {
                int r = q * 32 + ldrow;
                CP16(sA[buf ^ 1] + (r * PV_LDA + ldslot) * 2,
                     Asrc + (size_t)r * kHW + k0 + ldslot);
                CP16(sB[buf ^ 1] + (r * PV_LDA + ldslot) * 2,
                     Bsrc + (size_t)r * kHW + k0 + ldslot);
            }
            CP_COMMIT();
            CP_WAIT(1);
        } else {
            CP_WAIT(0);
        }
        __syncthreads();

        // per-chunk row scales (tile = i>>1); a0,a2 <-> row ra; a1,a3 <-> ra+8
        const int tile = i >> 1;
        __half2 ha[4], hb[4];
        #pragma unroll
        for (int mt = 0; mt < 4; mt++) {
            int ra = wm + mt * 16 + (lane >> 2);
            ha[mt] = __half2half2(__float2half_rn(alpha_s[ra * 33 + tile]));
            hb[mt] = __half2half2(__float2half_rn(alpha_s[(ra + 8) * 33 + tile]));
        }

        #pragma unroll
        for (int ks = 0; ks < 4; ks++) {
            uint32_t af[4][4], bf[4][2];
            #pragma unroll
            for (int mt = 0; mt < 4; mt++) {
                ldmx4(af[mt][0], af[mt][1], af[mt][2], af[mt][3],
                      sA[buf] + ((aRow + mt * 16) * PV_LDA + aCol + ks * 16) * 2);
                *(__half2*)&af[mt][0] = __hmul2(*(__half2*)&af[mt][0], ha[mt]);
                *(__half2*)&af[mt][1] = __hmul2(*(__half2*)&af[mt][1], hb[mt]);
                *(__half2*)&af[mt][2] = __hmul2(*(__half2*)&af[mt][2], ha[mt]);
                *(__half2*)&af[mt][3] = __hmul2(*(__half2*)&af[mt][3], hb[mt]);
            }
            #pragma unroll
            for (int np = 0; np < 2; np++)
                ldmx4(bf[np * 2][0], bf[np * 2][1], bf[np * 2 + 1][0], bf[np * 2 + 1][1],
                      sB[buf] + ((bRow + np * 16) * PV_LDA + bCol + ks * 16) * 2);
            #pragma unroll
            for (int mt = 0; mt < 4; mt++)
                #pragma unroll
                for (int nt = 0; nt < 4; nt++)
                    mma16816(acc[mt][nt], af[mt], bf[nt]);
        }
        __syncthreads();
    }

    float* stage = (float*)smem;          // [128][132] as [n][m]
    #pragma unroll
    for (int mt = 0; mt < 4; mt++)
        #pragma unroll
        for (int nt = 0; nt < 4; nt++)
            #pragma unroll
            for (int r = 0; r < 4; r++) {
                int m = wm + mt * 16 + (lane >> 2) + ((r >= 2) ? 8 : 0);
                int n = wn + nt * 8 + (lane & 3) * 2 + (r & 1);
                stage[n * 132 + m] = acc[mt][nt][r];
            }
    __syncthreads();

    const float g = __ldg(gamma);
    const size_t obofs = (size_t)bz * kHW * kC;
    #pragma unroll
    for (int q = 0; q < 16; q++) {
        int idx = tid + q * 256;
        int n   = idx >> 5;
        int m4  = (idx & 31) << 2;
        size_t o = obofs + (size_t)(n0 + n) * kHW + m0 + m4;
        float4 xv = *(const float4*)(x + o);
        const float* sp = stage + n * 132 + m4;
        *(float4*)(out + o) = make_float4(fmaf(g, sp[0], xv.x), fmaf(g, sp[1], xv.y),
                                          fmaf(g, sp[2], xv.z), fmaf(g, sp[3], xv.w));
    }
}

// ============ HMMA: V-proj NT (proven): vT = (x @ W3)^T ====================
__global__ void __launch_bounds__(256, 2) vproj_mma() {
    extern __shared__ char smem[];
    const uint32_t sb  = smem_u32(smem);
    const int tid  = threadIdx.x;
    const int lane = tid & 31, wid = tid >> 5;
    const int wm = (wid & 1) * 64, wn = (wid >> 1) * 32;
    const int n0 = blockIdx.x * 128, m0 = blockIdx.y * 128;

    const __half* Asrc = g_xh + (size_t)m0 * kC;
    const __half* Bsrc = g_w3T + (size_t)n0 * kC;

    const uint32_t sA[2] = {sb, sb + PV_ABUF};
    const uint32_t sB[2] = {sb + 2 * PV_ABUF, sb + 3 * PV_ABUF};

    const int ldrow  = tid >> 3;
    const int ldslot = (tid & 7) * 8;

    float acc[4][4][4];
    #pragma unroll
    for (int i = 0; i < 4; i++)
        #pragma unroll
        for (int j = 0; j < 4; j++)
            #pragma unroll
            for (int r = 0; r < 4; r++) acc[i][j][r] = 0.f;

    const int aRow = wm + (lane & 15);
    const int aCol = (lane >> 4) * 8;
    const int bRow = wn + ((lane >> 4) << 3) + (lane & 7);
    const int bCol = ((lane >> 3) & 1) * 8;

    #pragma unroll
    for (int q = 0; q < 4; q++) {
        int r = q * 32 + ldrow;
        CP16(sA[0] + (r * PV_LDA + ldslot) * 2, Asrc + (size_t)r * kC + ldslot);
        CP16(sB[0] + (r * PV_LDA + ldslot) * 2, Bsrc + (size_t)r * kC + ldslot);
    }
    CP_COMMIT();

    for (int i = 0; i < 8; i++) {
        const int buf = i & 1;
        if (i < 7) {
            const int k0 = (i + 1) * 64;
            #pragma unroll
            for (int q = 0; q < 4; q++) {
                int r = q * 32 + ldrow;
                CP16(sA[buf ^ 1] + (r * PV_LDA + ldslot) * 2,
                     Asrc + (size_t)r * kC + k0 + ldslot);
                CP16(sB[buf ^ 1] + (r * PV_LDA + ldslot) * 2,
                     Bsrc + (size_t)r * kC + k0 + ldslot);
            }
            CP_COMMIT();
            CP_WAIT(1);
        } else {
            CP_WAIT(0);
        }
        __syncthreads();

        #pragma unroll
        for (int ks = 0; ks < 4; ks++) {
            uint32_t af[4][4], bf[4][2];
            #pragma unroll
            for (int mt = 0; mt < 4; mt++)
                ldmx4(af[mt][0], af[mt][1], af[mt][2], af[mt][3],
                      sA[buf] + ((aRow + mt * 16) * PV_LDA + aCol + ks * 16) * 2);
            #pragma unroll
            for (int np = 0; np < 2; np++)
                ldmx4(bf[np * 2][0], bf[np * 2][1], bf[np * 2 + 1][0], bf[np * 2 + 1][1],
                      sB[buf] + ((bRow + np * 16) * PV_LDA + bCol + ks * 16) * 2);
            #pragma unroll
            for (int mt = 0; mt < 4; mt++)
                #pragma unroll
                for (int nt = 0; nt < 4; nt++)
                    mma16816(acc[mt][nt], af[mt], bf[nt]);
        }
        __syncthreads();
    }

    __half* stage = (__half*)smem;        // [128][136]
    constexpr int SLD = 136;
    #pragma unroll
    for (int mt = 0; mt < 4; mt++)
        #pragma unroll
        for (int nt = 0; nt < 4; nt++)
            #pragma unroll
            for (int r = 0; r < 4; r++) {
                int m = wm + mt * 16 + (lane >> 2) + ((r >= 2) ? 8 : 0);
                int n = wn + nt * 8 + (lane & 3) * 2 + (r & 1);
                stage[n * SLD + m] = __float2half_rn(acc[mt][nt][r]);
            }
    __syncthreads();

    const int bz = m0 >> 12;
    const int ml = m0 & 4095;
    #pragma unroll
    for (int q = 0; q < 8; q++) {
        int idx = tid + q * 256;
        int n   = idx >> 4;
        int m8  = (idx & 15) << 3;
        __half* dst = g_vT + ((size_t)bz * kC + n0 + n) * kHW + ml + m8;
        *(uint4*)dst = *(uint4*)(stage + n * SLD + m8);
    }
}

// ===== HMMA: q|k projection via 3-term split (proven), emits hi/lo =========
__global__ void __launch_bounds__(256, 2) qkproj_mma() {
    extern __shared__ char smem[];
    const uint32_t sb  = smem_u32(smem);
    const int tid  = threadIdx.x;
    const int lane = tid & 31, wid = tid >> 5;
    const int wm = (wid & 1) * 64, wn = (wid >> 1) * 32;
    const int m0 = blockIdx.y * 128;

    const uint32_t sA[2] = {sb, sb + PV_ABUF};
    const uint32_t sB[2] = {sb + 2 * PV_ABUF, sb + 3 * PV_ABUF};

    const int ldrow  = tid >> 3;
    const int ldslot = (tid & 7) * 8;

    float acc[4][4][4];
    #pragma unroll
    for (int i = 0; i < 4; i++)
        #pragma unroll
        for (int j = 0; j < 4; j++)
            #pragma unroll
            for (int r = 0; r < 4; r++) acc[i][j][r] = 0.f;

    const int aRow = wm + (lane & 15);
    const int aCol = (lane >> 4) * 8;
    const int bRow = wn + ((lane >> 4) << 3) + (lane & 7);
    const int bCol = ((lane >> 3) & 1) * 8;

#define QK_PREFETCH(i, buf) do {                                               \
    const int term = (i) >> 3, kc = (i) & 7;                                   \
    const __half* Ap = ((term == 1) ? g_xl : g_xh) + (size_t)m0 * kC + kc * 64; \
    const __half* Bp = ((term == 2) ? g_w12l : g_w12h) + kc * 64;              \
    _Pragma("unroll") for (int q = 0; q < 4; q++) {                            \
        int r = q * 32 + ldrow;                                                \
        CP16(sA[buf] + (r * PV_LDA + ldslot) * 2, Ap + (size_t)r * kC + ldslot); \
        CP16(sB[buf] + (r * PV_LDA + ldslot) * 2, Bp + (size_t)r * kC + ldslot); \
    }                                                                          \
    CP_COMMIT();                                                               \
} while (0)

    QK_PREFETCH(0, 0);
    for (int i = 0; i < 24; i++) {
        const int buf = i & 1;
        if (i < 23) { QK_PREFETCH(i + 1, buf ^ 1); CP_WAIT(1); }
        else        { CP_WAIT(0); }
        __syncthreads();

        #pragma unroll
        for (int ks = 0; ks < 4; ks++) {
            uint32_t af[4][4], bf[4][2];
            #pragma unroll
            for (int mt = 0; mt < 4; mt++)
                ldmx4(af[mt][0], af[mt][1], af[mt][2], af[mt][3],
                      sA[buf] + ((aRow + mt * 16) * PV_LDA + aCol + ks * 16) * 2);
            #pragma unroll
            for (int np = 0; np < 2; np++)
                ldmx4(bf[np * 2][0], bf[np * 2][1], bf[np * 2 + 1][0], bf[np * 2 + 1][1],
                      sB[buf] + ((bRow + np * 16) * PV_LDA + bCol + ks * 16) * 2);
            #pragma unroll
            for (int mt = 0; mt < 4; mt++)
                #pragma unroll
                for (int nt = 0; nt < 4; nt++)
                    mma16816(acc[mt][nt], af[mt], bf[nt]);
        }
        __syncthreads();
    }
#undef QK_PREFETCH

    float* stage = (float*)smem;          // [128][132]
    #pragma unroll
    for (int mt = 0; mt < 4; mt++)
        #pragma unroll
        for (int nt = 0; nt < 4; nt++)
            #pragma unroll
            for (int r = 0; r < 4; r++) {
                int m = wm + mt * 16 + (lane >> 2) + ((r >= 2) ? 8 : 0);
                int n = wn + nt * 8 + (lane & 3) * 2 + (r & 1);
                stage[m * 132 + n] = acc[mt][nt][r];
            }
    __syncthreads();

    #pragma unroll
    for (int q = 0; q < 16; q++) {
        int idx = tid + q * 256;
        int t   = idx >> 5;
        int c4  = (idx & 31) << 2;
        const float* sp = stage + t * 132 + c4;
        __half hi[4], lo[4];
        #pragma unroll
        for (int j = 0; j < 4; j++) {
            hi[j] = __float2half_rn(sp[j]);
            lo[j] = __float2half_rn(sp[j] - __half2float(hi[j]));
        }
        __half* base = (c4 < 64) ? (g_qs + (size_t)(m0 + t) * 128 + c4)
                                 : (g_ks + (size_t)(m0 + t) * 128 + (c4 - 64));
        *(uint2*)base        = *(uint2*)hi;
        *(uint2*)(base + 64) = *(uint2*)lo;
    }
}

// ========== exp_tiles v2: QK^T (3-term split) + register tile softmax ======
// Writes e = 2^(l*log2e - m_tile) fp16 to g_sh; (m_tile, s_tile) to g_mt/g_st.
__global__ void __launch_bounds__(256, 2) exp_tiles() {
    extern __shared__ char smem[];
    const uint32_t sb  = smem_u32(smem);
    const int tid  = threadIdx.x;
    const int lane = tid & 31, wid = tid >> 5;
    const int wm = (wid & 1) * 64, wn = (wid >> 1) * 32;
    const int n0 = blockIdx.x * 128, m0 = blockIdx.y * 128, bz = blockIdx.z;

    const __half* Asrc = g_qs + ((size_t)bz * kHW + m0) * 128;
    const __half* Bsrc = g_ks + ((size_t)bz * kHW + n0) * 128;

    const uint32_t sA[2] = {sb, sb + PV_ABUF};
    const uint32_t sB[2] = {sb + 2 * PV_ABUF, sb + 3 * PV_ABUF};

    const int ldrow  = tid >> 3;
    const int ldslot = (tid & 7) * 8;

    float acc[4][4][4];
    #pragma unroll
    for (int i = 0; i < 4; i++)
        #pragma unroll
        for (int j = 0; j < 4; j++)
            #pragma unroll
            for (int r = 0; r < 4; r++) acc[i][j][r] = 0.f;

    const int aRow = wm + (lane & 15);
    const int aCol = (lane >> 4) * 8;
    const int bRow = wn + ((lane >> 4) << 3) + (lane & 7);
    const int bCol = ((lane >> 3) & 1) * 8;

    const int AOFF[3] = {0, 64, 0};
    const int BOFF[3] = {0, 0, 64};

    #pragma unroll
    for (int q = 0; q < 4; q++) {
        int r = q * 32 + ldrow;
        CP16(sA[0] + (r * PV_LDA + ldslot) * 2, Asrc + (size_t)r * 128 + AOFF[0] + ldslot);
        CP16(sB[0] + (r * PV_LDA + ldslot) * 2, Bsrc + (size_t)r * 128 + BOFF[0] + ldslot);
    }
    CP_COMMIT();

    for (int i = 0; i < 3; i++) {
        const int buf = i & 1;
        if (i < 2) {
            #pragma unroll
            for (int q = 0; q < 4; q++) {
                int r = q * 32 + ldrow;
                CP16(sA[buf ^ 1] + (r * PV_LDA + ldslot) * 2,
                     Asrc + (size_t)r * 128 + AOFF[i + 1] + ldslot);
                CP16(sB[buf ^ 1] + (r * PV_LDA + ldslot) * 2,
                     Bsrc + (size_t)r * 128 + BOFF[i + 1] + ldslot);
            }
            CP_COMMIT();
            CP_WAIT(1);
        } else {
            CP_WAIT(0);
        }
        __syncthreads();

        #pragma unroll
        for (int ks = 0; ks < 4; ks++) {
            uint32_t af[4][4], bf[4][2];
            #pragma unroll
            for (int mt = 0; mt < 4; mt++)
                ldmx4(af[mt][0], af[mt][1], af[mt][2], af[mt][3],
                      sA[buf] + ((aRow + mt * 16) * PV_LDA + aCol + ks * 16) * 2);
            #pragma unroll
            for (int np = 0; np < 2; np++)
                ldmx4(bf[np * 2][0], bf[np * 2][1], bf[np * 2 + 1][0], bf[np * 2 + 1][1],
                      sB[buf] + ((bRow + np * 16) * PV_LDA + bCol + ks * 16) * 2);
            #pragma unroll
            for (int mt = 0; mt < 4; mt++)
                #pragma unroll
                for (int nt = 0; nt < 4; nt++)
                    mma16816(acc[mt][nt], af[mt], bf[nt]);
        }
        __syncthreads();
    }

    // --------- register-resident tile softmax stats + fp16 e staging -------
    __half* stageh = (__half*)smem;                        // [128][136] halves
    float*  pmax   = (float*)(smem + 128 * 136 * 2);       // [128][4]
    float*  psum   = (float*)(smem + 128 * 136 * 2 + 2048);// [128][4]
    float*  rowm2  = (float*)(smem + 128 * 136 * 2 + 4096);// [128]
    const int cg = wid >> 1;

    // phase 1: per-warp row max (4-lane shuffle reduce), cross-warp partials
    #pragma unroll
    for (int mt = 0; mt < 4; mt++) {
        float ma = -1e30f, mb = -1e30f;
        #pragma unroll
        for (int nt = 0; nt < 4; nt++) {
            ma = fmaxf(ma, fmaxf(acc[mt][nt][0], acc[mt][nt][1]));
            mb = fmaxf(mb, fmaxf(acc[mt][nt][2], acc[mt][nt][3]));
        }
        ma = fmaxf(ma, __shfl_xor_sync(0xffffffffu, ma, 1));
        ma = fmaxf(ma, __shfl_xor_sync(0xffffffffu, ma, 2));
        mb = fmaxf(mb, __shfl_xor_sync(0xffffffffu, mb, 1));
        mb = fmaxf(mb, __shfl_xor_sync(0xffffffffu, mb, 2));
        if ((lane & 3) == 0) {
            int ra = wm + mt * 16 + (lane >> 2);
            pmax[ra * 4 + cg]       = ma;
            pmax[(ra + 8) * 4 + cg] = mb;
        }
    }
    __syncthreads();
    if (tid < 128) {
        float m = fmaxf(fmaxf(pmax[tid * 4], pmax[tid * 4 + 1]),
                        fmaxf(pmax[tid * 4 + 2], pmax[tid * 4 + 3]));
        rowm2[tid] = m * LOG2E;
    }
    __syncthreads();

    // phase 2: exp in registers, stage fp16 e, partial sums
    #pragma unroll
    for (int mt = 0; mt < 4; mt++) {
        int ra = wm + mt * 16 + (lane >> 2);
        float m2a = rowm2[ra], m2b = rowm2[ra + 8];
        float sa = 0.f, sb2 = 0.f;
        #pragma unroll
        for (int nt = 0; nt < 4; nt++) {
            int col = wn + nt * 8 + (lane & 3) * 2;
            float e0 = exp2f_fast(fmaf(acc[mt][nt][0], LOG2E, -m2a));
            float e1 = exp2f_fast(fmaf(acc[mt][nt][1], LOG2E, -m2a));
            float e2 = exp2f_fast(fmaf(acc[mt][nt][2], LOG2E, -m2b));
            float e3 = exp2f_fast(fmaf(acc[mt][nt][3], LOG2E, -m2b));
            sa  += e0 + e1;
            sb2 += e2 + e3;
            *(__half2*)(stageh + ra * 136 + col)       = __floats2half2_rn(e0, e1);
            *(__half2*)(stageh + (ra + 8) * 136 + col) = __floats2half2_rn(e2, e3);
        }
        sa  += __shfl_xor_sync(0xffffffffu, sa, 1);
        sa  += __shfl_xor_sync(0xffffffffu, sa, 2);
        sb2 += __shfl_xor_sync(0xffffffffu, sb2, 1);
        sb2 += __shfl_xor_sync(0xffffffffu, sb2, 2);
        if ((lane & 3) == 0) {
            psum[ra * 4 + cg]       = sa;
            psum[(ra + 8) * 4 + cg] = sb2;
        }
    }
    __syncthreads();

    if (tid < 128) {
        float s = psum[tid * 4] + psum[tid * 4 + 1] + psum[tid * 4 + 2] + psum[tid * 4 + 3];
        size_t ridx = ((size_t)bz * kHW + m0 + tid) * 32 + (n0 >> 7);
        g_mt[ridx] = rowm2[tid];
        g_st[ridx] = s;
    }

    // phase 3: coalesced fp16 e writes
    __half* Pp = g_sh + (size_t)bz * kHW * kHW;
    #pragma unroll
    for (int q = 0; q < 8; q++) {
        int idx = tid + q * 256;          // 0..2047
        int r = idx >> 4, c = (idx & 15) * 8;
        *(uint4*)(Pp + (size_t)(m0 + r) * kHW + n0 + c) = *(uint4*)(stageh + r * 136 + c);
    }
}

// ===== per-row reduce: M = max m2_t, Z = sum s_t*2^(m2_t-M), alpha' fp16 ====
__global__ __launch_bounds__(256) void reduce_stats() {
    const int row  = blockIdx.x * 8 + (threadIdx.x >> 5);   // 16384 rows
    const int lane = threadIdx.x & 31;
    const size_t base = (size_t)row * 32;
    float m2 = g_mt[base + lane];
    float s  = g_st[base + lane];
    float M2 = m2;
    #pragma unroll
    for (int o = 16; o > 0; o >>= 1) M2 = fmaxf(M2, __shfl_xor_sync(0xffffffffu, M2, o));
    float a = exp2f_fast(m2 - M2);
    float z = s * a;
    #pragma unroll
    for (int o = 16; o > 0; o >>= 1) z += __shfl_xor_sync(0xffffffffu, z, o);
    g_scale[base + lane] = __float2half_rn(a / z);
}

// ---------------------------------------------------------------------------
extern "C" void kernel_launch(void* const* d_in, const int* in_sizes, int n_in,
                              void* d_out, int out_size) {
    const float* x     = (const float*)d_in[0];
    const float* W1    = (const float*)d_in[1];
    const float* W2    = (const float*)d_in[2];
    const float* W3    = (const float*)d_in[3];
    const float* gamma = (const float*)d_in[4];
    float* out = (float*)d_out;

    cudaFuncSetAttribute(pv_mma, cudaFuncAttributeMaxDynamicSharedMemorySize, PV2_SMEM);
    cudaFuncSetAttribute(vproj_mma, cudaFuncAttributeMaxDynamicSharedMemorySize, PV_SMEM);
    cudaFuncSetAttribute(qkproj_mma, cudaFuncAttributeMaxDynamicSharedMemorySize, PV_SMEM);
    cudaFuncSetAttribute(exp_tiles, cudaFuncAttributeMaxDynamicSharedMemorySize, PV_SMEM);

    concat_w_split<<<256, 256>>>(W1, W2);                 // W12^T hi/lo
    to_half_x<<<8192, 256>>>(x);                          // x hi/lo fp16
    transpose_w3<<<dim3(16, 16), 256>>>(W3);              // W3^T fp16
    qkproj_mma<<<dim3(1, 128), 256, PV_SMEM>>>();         // q,k hi/lo (proven)
    vproj_mma<<<dim3(4, 128), 256, PV_SMEM>>>();          // vT fp16 (proven)
    exp_tiles<<<dim3(32, 32, 4), 256, PV_SMEM>>>();       // e tiles + reg stats
    reduce_stats<<<2048, 256>>>();                        // M, Z, alpha'
    pv_mma<<<dim3(4, 32, 4), 256, PV2_SMEM>>>(x, gamma, out);
}

// round 13
// speedup vs baseline: 1.1275x; 1.0056x over previous
#include <cuda_runtime.h>
#include <cuda_fp16.h>
#include <cstdint>

// ---------------------------------------------------------------------------
// PositionAttentionModule: B=4, HW=4096, C=512, Cr=64
//   prep_all             x->hi/lo fp16, W12^T hi/lo, W3^T fp16 (merged launch)
//   qkproj_mma           3-term split HMMA -> q,k hi/lo fp16 (proven)
//   exp_vproj            MERGED LAUNCH: exp_tiles (QK^T + register tile
//                        softmax stats -> e fp16) CONCURRENT WITH vproj HMMA
//   reduce_stats         per-row M, Z; alpha'[row][tile] (proven)
//   pv_mma               E = (e*alpha') @ v, alpha' in-mainloop (proven R12)
// Rule R7: device globals referenced ONLY inside kernel bodies.
// R12 lesson: serial launches waste concurrency; merge independent kernels.
// ---------------------------------------------------------------------------

constexpr int kHW  = 4096;
constexpr int kC   = 512;
constexpr int kTok = 4 * kHW;   // 16384

__device__ __half g_qs  [kTok * 128];                   // 4 MB q split [hi|lo]
__device__ __half g_ks  [kTok * 128];                   // 4 MB k split [hi|lo]
__device__ __half g_sh  [(size_t)4 * kHW * kHW];        // 128 MB fp16 e-values
__device__ float  g_mt  [(size_t)kTok * 32];            // 2 MB per-(row,tile) max
__device__ float  g_st  [(size_t)kTok * 32];            // 2 MB per-(row,tile) sum
__device__ __half g_scale[(size_t)kTok * 32];           // 1 MB alpha'
__device__ __half g_vT  [(size_t)4 * kC * kHW];         // 16 MB vT[b][n][i]
__device__ __half g_xh  [(size_t)kTok * kC];            // 16 MB x hi fp16
__device__ __half g_xl  [(size_t)kTok * kC];            // 16 MB x lo fp16
__device__ __half g_w12h[128 * kC];                     // 128 KB W12^T hi
__device__ __half g_w12l[128 * kC];                     // 128 KB W12^T lo
__device__ __half g_w3T [kC * kC];                      // 512 KB W3^T fp16

// ============================ PTX helpers ==================================
__device__ __forceinline__ uint32_t smem_u32(const void* p) {
    uint32_t a;
    asm("{ .reg .u64 t; cvta.to.shared.u64 t, %1; cvt.u32.u64 %0, t; }"
        : "=r"(a) : "l"(p));
    return a;
}
__device__ __forceinline__ void ldmx4(uint32_t& r0, uint32_t& r1, uint32_t& r2,
                                      uint32_t& r3, uint32_t a) {
    asm volatile("ldmatrix.sync.aligned.m8n8.x4.shared.b16 {%0,%1,%2,%3}, [%4];"
                 : "=r"(r0), "=r"(r1), "=r"(r2), "=r"(r3) : "r"(a));
}
__device__ __forceinline__ void mma16816(float* c, const uint32_t* a,
                                         const uint32_t* b) {
    asm volatile(
        "mma.sync.aligned.m16n8k16.row.col.f32.f16.f16.f32 "
        "{%0,%1,%2,%3}, {%4,%5,%6,%7}, {%8,%9}, {%0,%1,%2,%3};"
        : "+f"(c[0]), "+f"(c[1]), "+f"(c[2]), "+f"(c[3])
        : "r"(a[0]), "r"(a[1]), "r"(a[2]), "r"(a[3]), "r"(b[0]), "r"(b[1]));
}
#define CP16(sm, gp) \
    asm volatile("cp.async.cg.shared.global [%0], [%1], 16;" :: "r"(sm), "l"(gp))
#define CP_COMMIT() asm volatile("cp.async.commit_group;" ::: "memory")
#define CP_WAIT(n)  asm volatile("cp.async.wait_group %0;" :: "n"(n) : "memory")

__device__ __forceinline__ float exp2f_fast(float f) {
    f = fmaxf(f, -126.f);
    float n = floorf(f);
    float r = f - n;
    float p = 1.5252734e-5f;
    p = fmaf(p, r, 1.5403530e-4f);
    p = fmaf(p, r, 1.3333558e-3f);
    p = fmaf(p, r, 9.6181291e-3f);
    p = fmaf(p, r, 5.5504109e-2f);
    p = fmaf(p, r, 2.4022651e-1f);
    p = fmaf(p, r, 6.9314718e-1f);
    p = fmaf(p, r, 1.0f);
    return p * __int_as_float((((int)n) + 127) << 23);
}
constexpr float LOG2E = 1.4426950408889634f;

// ============ HMMA NT skeleton constants ===================================
constexpr int PV_LDA   = 72;                        // halves, padded
constexpr int PV_ABUF  = 128 * PV_LDA * 2;          // 18432 B
constexpr int PV_SMEM  = 4 * PV_ABUF;               // 73728 B
constexpr int PV2_SMEM = PV_SMEM + 128 * 33 * 4;    // + alpha_s = 90624 B

// ================== prep_all: merged elementwise prep ======================
// blocks [0,8192): to_half_x ; [8192,8448): concat_w_split ; [8448,8704): W3^T
__global__ __launch_bounds__(256) void prep_all(const float* __restrict__ x,
                                                const float* __restrict__ W1,
                                                const float* __restrict__ W2,
                                                const float* __restrict__ W3) {
    __shared__ float t[32][33];
    const int blk = blockIdx.x;
    if (blk < 8192) {
        int idx = blk * 256 + threadIdx.x;
        float4 v = *(const float4*)(x + (size_t)idx * 4);
        __half h0 = __float2half_rn(v.x), h1 = __float2half_rn(v.y);
        __half h2 = __float2half_rn(v.z), h3 = __float2half_rn(v.w);
        __half2* dh = (__half2*)(g_xh + (size_t)idx * 4);
        dh[0] = __halves2half2(h0, h1);
        dh[1] = __halves2half2(h2, h3);
        __half2* dl = (__half2*)(g_xl + (size_t)idx * 4);
        dl[0] = __floats2half2_rn(v.x - __half2float(h0), v.y - __half2float(h1));
        dl[1] = __floats2half2_rn(v.z - __half2float(h2), v.w - __half2float(h3));
    } else if (blk < 8448) {
        int idx = (blk - 8192) * 256 + threadIdx.x;     // < 65536
        int n = idx >> 9, k = idx & 511;
        float v = (n < 64) ? W1[k * 64 + n] : W2[k * 64 + (n - 64)];
        __half hi = __float2half_rn(v);
        __half lo = __float2half_rn(v - __half2float(hi));
        g_w12h[idx] = hi;
        g_w12l[idx] = lo;
    } else {
        int id = blk - 8448;                            // 0..255
        const int n0 = (id & 15) * 32;
        const int k0 = (id >> 4) * 32;
        const int tx = threadIdx.x & 31, ty = threadIdx.x >> 5;
        #pragma unroll
        for (int j = 0; j < 4; j++) {
            int kk = ty + j * 8;
            t[kk][tx] = W3[(size_t)(k0 + kk) * kC + n0 + tx];
        }
        __syncthreads();
        #pragma unroll
        for (int j = 0; j < 4; j++) {
            int nn = ty + j * 8;
            g_w3T[(size_t)(n0 + nn) * kC + k0 + tx] = __float2half_rn(t[tx][nn]);
        }
    }
}

// ===== HMMA: q|k projection via 3-term split (proven), emits hi/lo =========
__global__ void __launch_bounds__(256, 2) qkproj_mma() {
    extern __shared__ char smem[];
    const uint32_t sb  = smem_u32(smem);
    const int tid  = threadIdx.x;
    const int lane = tid & 31, wid = tid >> 5;
    const int wm = (wid & 1) * 64, wn = (wid >> 1) * 32;
    const int m0 = blockIdx.y * 128;

    const uint32_t sA[2] = {sb, sb + PV_ABUF};
    const uint32_t sB[2] = {sb + 2 * PV_ABUF, sb + 3 * PV_ABUF};

    const int ldrow  = tid >> 3;
    const int ldslot = (tid & 7) * 8;

    float acc[4][4][4];
    #pragma unroll
    for (int i = 0; i < 4; i++)
        #pragma unroll
        for (int j = 0; j < 4; j++)
            #pragma unroll
            for (int r = 0; r < 4; r++) acc[i][j][r] = 0.f;

    const int aRow = wm + (lane & 15);
    const int aCol = (lane >> 4) * 8;
    const int bRow = wn + ((lane >> 4) << 3) + (lane & 7);
    const int bCol = ((lane >> 3) & 1) * 8;

#define QK_PREFETCH(i, buf) do {                                               \
    const int term = (i) >> 3, kc = (i) & 7;                                   \
    const __half* Ap = ((term == 1) ? g_xl : g_xh) + (size_t)m0 * kC + kc * 64; \
    const __half* Bp = ((term == 2) ? g_w12l : g_w12h) + kc * 64;              \
    _Pragma("unroll") for (int q = 0; q < 4; q++) {                            \
        int r = q * 32 + ldrow;                                                \
        CP16(sA[buf] + (r * PV_LDA + ldslot) * 2, Ap + (size_t)r * kC + ldslot); \
        CP16(sB[buf] + (r * PV_LDA + ldslot) * 2, Bp + (size_t)r * kC + ldslot); \
    }                                                                          \
    CP_COMMIT();                                                               \
} while (0)

    QK_PREFETCH(0, 0);
    for (int i = 0; i < 24; i++) {
        const int buf = i & 1;
        if (i < 23) { QK_PREFETCH(i + 1, buf ^ 1); CP_WAIT(1); }
        else        { CP_WAIT(0); }
        __syncthreads();

        #pragma unroll
        for (int ks = 0; ks < 4; ks++) {
            uint32_t af[4][4], bf[4][2];
            #pragma unroll
            for (int mt = 0; mt < 4; mt++)
                ldmx4(af[mt][0], af[mt][1], af[mt][2], af[mt][3],
                      sA[buf] + ((aRow + mt * 16) * PV_LDA + aCol + ks * 16) * 2);
            #pragma unroll
            for (int np = 0; np < 2; np++)
                ldmx4(bf[np * 2][0], bf[np * 2][1], bf[np * 2 + 1][0], bf[np * 2 + 1][1],
                      sB[buf] + ((bRow + np * 16) * PV_LDA + bCol + ks * 16) * 2);
            #pragma unroll
            for (int mt = 0; mt < 4; mt++)
                #pragma unroll
                for (int nt = 0; nt < 4; nt++)
                    mma16816(acc[mt][nt], af[mt], bf[nt]);
        }
        __syncthreads();
    }
#undef QK_PREFETCH

    float* stage = (float*)smem;          // [128][132]
    #pragma unroll
    for (int mt = 0; mt < 4; mt++)
        #pragma unroll
        for (int nt = 0; nt < 4; nt++)
            #pragma unroll
            for (int r = 0; r < 4; r++) {
                int m = wm + mt * 16 + (lane >> 2) + ((r >= 2) ? 8 : 0);
                int n = wn + nt * 8 + (lane & 3) * 2 + (r & 1);
                stage[m * 132 + n] = acc[mt][nt][r];
            }
    __syncthreads();

    #pragma unroll
    for (int q = 0; q < 16; q++) {
        int idx = tid + q * 256;
        int t   = idx >> 5;
        int c4  = (idx & 31) << 2;
        const float* sp = stage + t * 132 + c4;
        __half hi[4], lo[4];
        #pragma unroll
        for (int j = 0; j < 4; j++) {
            hi[j] = __float2half_rn(sp[j]);
            lo[j] = __float2half_rn(sp[j] - __half2float(hi[j]));
        }
        __half* base = (c4 < 64) ? (g_qs + (size_t)(m0 + t) * 128 + c4)
                                 : (g_ks + (size_t)(m0 + t) * 128 + (c4 - 64));
        *(uint2*)base        = *(uint2*)hi;
        *(uint2*)(base + 64) = *(uint2*)lo;
    }
}

// ======= MERGED: exp_tiles (blocks 0..4095) + vproj (blocks 4096..4607) ====
__global__ void __launch_bounds__(256, 2) exp_vproj() {
    extern __shared__ char smem[];
    const uint32_t sb  = smem_u32(smem);
    const int tid  = threadIdx.x;
    const int lane = tid & 31, wid = tid >> 5;
    const int wm = (wid & 1) * 64, wn = (wid >> 1) * 32;

    const uint32_t sA[2] = {sb, sb + PV_ABUF};
    const uint32_t sB[2] = {sb + 2 * PV_ABUF, sb + 3 * PV_ABUF};
    const int ldrow  = tid >> 3;
    const int ldslot = (tid & 7) * 8;

    const int aRow = wm + (lane & 15);
    const int aCol = (lane >> 4) * 8;
    const int bRow = wn + ((lane >> 4) << 3) + (lane & 7);
    const int bCol = ((lane >> 3) & 1) * 8;

    float acc[4][4][4];
    #pragma unroll
    for (int i = 0; i < 4; i++)
        #pragma unroll
        for (int j = 0; j < 4; j++)
            #pragma unroll
            for (int r = 0; r < 4; r++) acc[i][j][r] = 0.f;

    const int id = blockIdx.x;

    if (id < 4096) {
        // ---------------- exp_tiles path (proven R12 body) -----------------
        const int bz = id >> 10;
        const int m0 = ((id >> 5) & 31) * 128;
        const int n0 = (id & 31) * 128;

        const __half* Asrc = g_qs + ((size_t)bz * kHW + m0) * 128;
        const __half* Bsrc = g_ks + ((size_t)bz * kHW + n0) * 128;

        const int AOFF[3] = {0, 64, 0};
        const int BOFF[3] = {0, 0, 64};

        #pragma unroll
        for (int q = 0; q < 4; q++) {
            int r = q * 32 + ldrow;
            CP16(sA[0] + (r * PV_LDA + ldslot) * 2, Asrc + (size_t)r * 128 + AOFF[0] + ldslot);
            CP16(sB[0] + (r * PV_LDA + ldslot) * 2, Bsrc + (size_t)r * 128 + BOFF[0] + ldslot);
        }
        CP_COMMIT();

        for (int i = 0; i < 3; i++) {
            const int buf = i & 1;
            if (i < 2) {
                #pragma unroll
                for (int q = 0; q < 4; q++) {
                    int r = q * 32 + ldrow;
                    CP16(sA[buf ^ 1] + (r * PV_LDA + ldslot) * 2,
                         Asrc + (size_t)r * 128 + AOFF[i + 1] + ldslot);
                    CP16(sB[buf ^ 1] + (r * PV_LDA + ldslot) * 2,
                         Bsrc + (size_t)r * 128 + BOFF[i + 1] + ldslot);
                }
                CP_COMMIT();
                CP_WAIT(1);
            } else {
                CP_WAIT(0);
            }
            __syncthreads();

            #pragma unroll
            for (int ks = 0; ks < 4; ks++) {
                uint32_t af[4][4], bf[4][2];
                #pragma unroll
                for (int mt = 0; mt < 4; mt++)
                    ldmx4(af[mt][0], af[mt][1], af[mt][2], af[mt][3],
                          sA[buf] + ((aRow + mt * 16) * PV_LDA + aCol + ks * 16) * 2);
                #pragma unroll
                for (int np = 0; np < 2; np++)
                    ldmx4(bf[np * 2][0], bf[np * 2][1], bf[np * 2 + 1][0], bf[np * 2 + 1][1],
                          sB[buf] + ((bRow + np * 16) * PV_LDA + bCol + ks * 16) * 2);
                #pragma unroll
                for (int mt = 0; mt < 4; mt++)
                    #pragma unroll
                    for (int nt = 0; nt < 4; nt++)
                        mma16816(acc[mt][nt], af[mt], bf[nt]);
            }
            __syncthreads();
        }

        // register-resident tile softmax stats + fp16 e staging
        __half* stageh = (__half*)smem;                        // [128][136]
        float*  pmax   = (float*)(smem + 128 * 136 * 2);       // [128][4]
        float*  psum   = (float*)(smem + 128 * 136 * 2 + 2048);// [128][4]
        float*  rowm2  = (float*)(smem + 128 * 136 * 2 + 4096);// [128]
        const int cg = wid >> 1;

        #pragma unroll
        for (int mt = 0; mt < 4; mt++) {
            float ma = -1e30f, mb = -1e30f;
            #pragma unroll
            for (int nt = 0; nt < 4; nt++) {
                ma = fmaxf(ma, fmaxf(acc[mt][nt][0], acc[mt][nt][1]));
                mb = fmaxf(mb, fmaxf(acc[mt][nt][2], acc[mt][nt][3]));
            }
            ma = fmaxf(ma, __shfl_xor_sync(0xffffffffu, ma, 1));
            ma = fmaxf(ma, __shfl_xor_sync(0xffffffffu, ma, 2));
            mb = fmaxf(mb, __shfl_xor_sync(0xffffffffu, mb, 1));
            mb = fmaxf(mb, __shfl_xor_sync(0xffffffffu, mb, 2));
            if ((lane & 3) == 0) {
                int ra = wm + mt * 16 + (lane >> 2);
                pmax[ra * 4 + cg]       = ma;
                pmax[(ra + 8) * 4 + cg] = mb;
            }
        }
        __syncthreads();
        if (tid < 128) {
            float m = fmaxf(fmaxf(pmax[tid * 4], pmax[tid * 4 + 1]),
                            fmaxf(pmax[tid * 4 + 2], pmax[tid * 4 + 3]));
            rowm2[tid] = m * LOG2E;
        }
        __syncthreads();

        #pragma unroll
        for (int mt = 0; mt < 4; mt++) {
            int ra = wm + mt * 16 + (lane >> 2);
            float m2a = rowm2[ra], m2b = rowm2[ra + 8];
            float sa = 0.f, sb2 = 0.f;
            #pragma unroll
            for (int nt = 0; nt < 4; nt++) {
                int col = wn + nt * 8 + (lane & 3) * 2;
                float e0 = exp2f_fast(fmaf(acc[mt][nt][0], LOG2E, -m2a));
                float e1 = exp2f_fast(fmaf(acc[mt][nt][1], LOG2E, -m2a));
                float e2 = exp2f_fast(fmaf(acc[mt][nt][2], LOG2E, -m2b));
                float e3 = exp2f_fast(fmaf(acc[mt][nt][3], LOG2E, -m2b));
                sa  += e0 + e1;
                sb2 += e2 + e3;
                *(__half2*)(stageh + ra * 136 + col)       = __floats2half2_rn(e0, e1);
                *(__half2*)(stageh + (ra + 8) * 136 + col) = __floats2half2_rn(e2, e3);
            }
            sa  += __shfl_xor_sync(0xffffffffu, sa, 1);
            sa  += __shfl_xor_sync(0xffffffffu, sa, 2);
            sb2 += __shfl_xor_sync(0xffffffffu, sb2, 1);
            sb2 += __shfl_xor_sync(0xffffffffu, sb2, 2);
            if ((lane & 3) == 0) {
                psum[ra * 4 + cg]       = sa;
                psum[(ra + 8) * 4 + cg] = sb2;
            }
        }
        __syncthreads();

        if (tid < 128) {
            float s = psum[tid * 4] + psum[tid * 4 + 1] + psum[tid * 4 + 2] + psum[tid * 4 + 3];
            size_t ridx = ((size_t)bz * kHW + m0 + tid) * 32 + (n0 >> 7);
            g_mt[ridx] = rowm2[tid];
            g_st[ridx] = s;
        }

        __half* Pp = g_sh + (size_t)bz * kHW * kHW;
        #pragma unroll
        for (int q = 0; q < 8; q++) {
            int idx = tid + q * 256;
            int r = idx >> 4, c = (idx & 15) * 8;
            *(uint4*)(Pp + (size_t)(m0 + r) * kHW + n0 + c) = *(uint4*)(stageh + r * 136 + c);
        }
    } else {
        // ---------------- vproj path (proven body) -------------------------
        const int id2 = id - 4096;                       // 0..511
        const int n0 = (id2 & 3) * 128;
        const int m0 = (id2 >> 2) * 128;

        const __half* Asrc = g_xh + (size_t)m0 * kC;
        const __half* Bsrc = g_w3T + (size_t)n0 * kC;

        #pragma unroll
        for (int q = 0; q < 4; q++) {
            int r = q * 32 + ldrow;
            CP16(sA[0] + (r * PV_LDA + ldslot) * 2, Asrc + (size_t)r * kC + ldslot);
            CP16(sB[0] + (r * PV_LDA + ldslot) * 2, Bsrc + (size_t)r * kC + ldslot);
        }
        CP_COMMIT();

        for (int i = 0; i < 8; i++) {
            const int buf = i & 1;
            if (i < 7) {
                const int k0 = (i + 1) * 64;
                #pragma unroll
                for (int q = 0; q < 4; q++) {
                    int r = q * 32 + ldrow;
                    CP16(sA[buf ^ 1] + (r * PV_LDA + ldslot) * 2,
                         Asrc + (size_t)r * kC + k0 + ldslot);
                    CP16(sB[buf ^ 1] + (r * PV_LDA + ldslot) * 2,
                         Bsrc + (size_t)r * kC + k0 + ldslot);
                }
                CP_COMMIT();
                CP_WAIT(1);
            } else {
                CP_WAIT(0);
            }
            __syncthreads();

            #pragma unroll
            for (int ks = 0; ks < 4; ks++) {
                uint32_t af[4][4], bf[4][2];
                #pragma unroll
                for (int mt = 0; mt < 4; mt++)
                    ldmx4(af[mt][0], af[mt][1], af[mt][2], af[mt][3],
                          sA[buf] + ((aRow + mt * 16) * PV_LDA + aCol + ks * 16) * 2);
                #pragma unroll
                for (int np = 0; np < 2; np++)
                    ldmx4(bf[np * 2][0], bf[np * 2][1], bf[np * 2 + 1][0], bf[np * 2 + 1][1],
                          sB[buf] + ((bRow + np * 16) * PV_LDA + bCol + ks * 16) * 2);
                #pragma unroll
                for (int mt = 0; mt < 4; mt++)
                    #pragma unroll
                    for (int nt = 0; nt < 4; nt++)
                        mma16816(acc[mt][nt], af[mt], bf[nt]);
            }
            __syncthreads();
        }

        __half* stage = (__half*)smem;        // [128][136]
        constexpr int SLD = 136;
        #pragma unroll
        for (int mt = 0; mt < 4; mt++)
            #pragma unroll
            for (int nt = 0; nt < 4; nt++)
                #pragma unroll
                for (int r = 0; r < 4; r++) {
                    int m = wm + mt * 16 + (lane >> 2) + ((r >= 2) ? 8 : 0);
                    int n = wn + nt * 8 + (lane & 3) * 2 + (r & 1);
                    stage[n * SLD + m] = __float2half_rn(acc[mt][nt][r]);
                }
        __syncthreads();

        const int bz = m0 >> 12;
        const int ml = m0 & 4095;
        #pragma unroll
        for (int q = 0; q < 8; q++) {
            int idx = tid + q * 256;
            int n   = idx >> 4;
            int m8  = (idx & 15) << 3;
            __half* dst = g_vT + ((size_t)bz * kC + n0 + n) * kHW + ml + m8;
            *(uint4*)dst = *(uint4*)(stage + n * SLD + m8);
        }
    }
}

// ===== per-row reduce: M = max m2_t, Z = sum s_t*2^(m2_t-M), alpha' fp16 ====
__global__ __launch_bounds__(256) void reduce_stats() {
    const int row  = blockIdx.x * 8 + (threadIdx.x >> 5);   // 16384 rows
    const int lane = threadIdx.x & 31;
    const size_t base = (size_t)row * 32;
    float m2 = g_mt[base + lane];
    float s  = g_st[base + lane];
    float M2 = m2;
    #pragma unroll
    for (int o = 16; o > 0; o >>= 1) M2 = fmaxf(M2, __shfl_xor_sync(0xffffffffu, M2, o));
    float a = exp2f_fast(m2 - M2);
    float z = s * a;
    #pragma unroll
    for (int o = 16; o > 0; o >>= 1) z += __shfl_xor_sync(0xffffffffu, z, o);
    g_scale[base + lane] = __float2half_rn(a / z);
}

// ========= pv_mma: E = (e*alpha') @ v, alpha' applied in mainloop (proven) ==
__global__ void __launch_bounds__(256, 2)
pv_mma(const float* __restrict__ x, const float* __restrict__ gamma,
       float* __restrict__ out) {
    extern __shared__ char smem[];
    const uint32_t sb  = smem_u32(smem);
    const int tid  = threadIdx.x;
    const int lane = tid & 31, wid = tid >> 5;
    const int wm = (wid & 1) * 64, wn = (wid >> 1) * 32;
    const int n0 = blockIdx.x * 128, m0 = blockIdx.y * 128, bz = blockIdx.z;

    const __half* Asrc = g_sh + (size_t)bz * kHW * kHW + (size_t)m0 * kHW;
    const __half* Bsrc = g_vT + (size_t)bz * kC * kHW + (size_t)n0 * kHW;

    const uint32_t sA[2] = {sb, sb + PV_ABUF};
    const uint32_t sB[2] = {sb + 2 * PV_ABUF, sb + 3 * PV_ABUF};
    float* alpha_s = (float*)(smem + 4 * PV_ABUF);   // [128][33]

    const int ldrow  = tid >> 3;
    const int ldslot = (tid & 7) * 8;

    #pragma unroll
    for (int q = 0; q < 16; q++) {
        int idx = tid + q * 256;
        int r = idx >> 5, t = idx & 31;
        alpha_s[r * 33 + t] =
            __half2float(g_scale[((size_t)bz * kHW + m0 + r) * 32 + t]);
    }

    float acc[4][4][4];
    #pragma unroll
    for (int i = 0; i < 4; i++)
        #pragma unroll
        for (int j = 0; j < 4; j++)
            #pragma unroll
            for (int r = 0; r < 4; r++) acc[i][j][r] = 0.f;

    const int aRow = wm + (lane & 15);
    const int aCol = (lane >> 4) * 8;
    const int bRow = wn + ((lane >> 4) << 3) + (lane & 7);
    const int bCol = ((lane >> 3) & 1) * 8;

    #pragma unroll
    for (int q = 0; q < 4; q++) {
        int r = q * 32 + ldrow;
        CP16(sA[0] + (r * PV_LDA + ldslot) * 2, Asrc + (size_t)r * kHW + ldslot);
        CP16(sB[0] + (r * PV_LDA + ldslot) * 2, Bsrc + (size_t)r * kHW + ldslot);
    }
    CP_COMMIT();

    for (int i = 0; i < 64; i++) {
        const int buf = i & 1;
        if (i < 63) {
            const int k0 = (i + 1) * 64;
            #pragma unroll
            for (int q = 0; q < 4; q++) {
                int r = q * 32 + ldrow;
                CP16(sA[buf ^ 1] + (r * PV_LDA + ldslot) * 2,
                     Asrc + (size_t)r * kHW + k0 + ldslot);
                CP16(sB[buf ^ 1] + (r * PV_LDA + ldslot) * 2,
                     Bsrc + (size_t)r * kHW + k0 + ldslot);
            }
            CP_COMMIT();
            CP_WAIT(1);
        } else {
            CP_WAIT(0);
        }
        __syncthreads();

        const int tile = i >> 1;
        __half2 ha[4], hb[4];
        #pragma unroll
        for (int mt = 0; mt < 4; mt++) {
            int ra = wm + mt * 16 + (lane >> 2);
            ha[mt] = __half2half2(__float2half_rn(alpha_s[ra * 33 + tile]));
            hb[mt] = __half2half2(__float2half_rn(alpha_s[(ra + 8) * 33 + tile]));
        }

        #pragma unroll
        for (int ks = 0; ks < 4; ks++) {
            uint32_t af[4][4], bf[4][2];
            #pragma unroll
            for (int mt = 0; mt < 4; mt++) {
                ldmx4(af[mt][0], af[mt][1], af[mt][2], af[mt][3],
                      sA[buf] + ((aRow + mt * 16) * PV_LDA + aCol + ks * 16) * 2);
                *(__half2*)&af[mt][0] = __hmul2(*(__half2*)&af[mt][0], ha[mt]);
                *(__half2*)&af[mt][1] = __hmul2(*(__half2*)&af[mt][1], hb[mt]);
                *(__half2*)&af[mt][2] = __hmul2(*(__half2*)&af[mt][2], ha[mt]);
                *(__half2*)&af[mt][3] = __hmul2(*(__half2*)&af[mt][3], hb[mt]);
            }
            #pragma unroll
            for (int np = 0; np < 2; np++)
                ldmx4(bf[np * 2][0], bf[np * 2][1], bf[np * 2 + 1][0], bf[np * 2 + 1][1],
                      sB[buf] + ((bRow + np * 16) * PV_LDA + bCol + ks * 16) * 2);
            #pragma unroll
            for (int mt = 0; mt < 4; mt++)
                #pragma unroll
                for (int nt = 0; nt < 4; nt++)
                    mma16816(acc[mt][nt], af[mt], bf[nt]);
        }
        __syncthreads();
    }

    float* stage = (float*)smem;          // [128][132] as [n][m]
    #pragma unroll
    for (int mt = 0; mt < 4; mt++)
        #pragma unroll
        for (int nt = 0; nt < 4; nt++)
            #pragma unroll
            for (int r = 0; r < 4; r++) {
                int m = wm + mt * 16 + (lane >> 2) + ((r >= 2) ? 8 : 0);
                int n = wn + nt * 8 + (lane & 3) * 2 + (r & 1);
                stage[n * 132 + m] = acc[mt][nt][r];
            }
    __syncthreads();

    const float g = __ldg(gamma);
    const size_t obofs = (size_t)bz * kHW * kC;
    #pragma unroll
    for (int q = 0; q < 16; q++) {
        int idx = tid + q * 256;
        int n   = idx >> 5;
        int m4  = (idx & 31) << 2;
        size_t o = obofs + (size_t)(n0 + n) * kHW + m0 + m4;
        float4 xv = *(const float4*)(x + o);
        const float* sp = stage + n * 132 + m4;
        *(float4*)(out + o) = make_float4(fmaf(g, sp[0], xv.x), fmaf(g, sp[1], xv.y),
                                          fmaf(g, sp[2], xv.z), fmaf(g, sp[3], xv.w));
    }
}

// ---------------------------------------------------------------------------
extern "C" void kernel_launch(void* const* d_in, const int* in_sizes, int n_in,
                              void* d_out, int out_size) {
    const float* x     = (const float*)d_in[0];
    const float* W1    = (const float*)d_in[1];
    const float* W2    = (const float*)d_in[2];
    const float* W3    = (const float*)d_in[3];
    const float* gamma = (const float*)d_in[4];
    float* out = (float*)d_out;

    cudaFuncSetAttribute(pv_mma, cudaFuncAttributeMaxDynamicSharedMemorySize, PV2_SMEM);
    cudaFuncSetAttribute(qkproj_mma, cudaFuncAttributeMaxDynamicSharedMemorySize, PV_SMEM);
    cudaFuncSetAttribute(exp_vproj, cudaFuncAttributeMaxDynamicSharedMemorySize, PV_SMEM);

    prep_all<<<8704, 256>>>(x, W1, W2, W3);               // merged prep
    qkproj_mma<<<dim3(1, 128), 256, PV_SMEM>>>();         // q,k hi/lo (proven)
    exp_vproj<<<4608, 256, PV_SMEM>>>();                  // exp_tiles || vproj
    reduce_stats<<<2048, 256>>>();                        // M, Z, alpha'
    pv_mma<<<dim3(4, 32, 4), 256, PV2_SMEM>>>(x, gamma, out);
}

// round 14
// speedup vs baseline: 1.1579x; 1.0270x over previous
#include <cuda_runtime.h>
#include <cuda_fp16.h>
#include <cstdint>

// ---------------------------------------------------------------------------
// PositionAttentionModule: B=4, HW=4096, C=512, Cr=64
//   prep_all             x->hi/lo fp16, W12^T hi/lo, W3^T fp16 (merged)
//   qkproj_mma           3-term split HMMA -> q,k hi/lo fp16 (proven)
//   exp_vproj            exp_tiles (QK^T + tile softmax -> e fp16) || vproj
//   reduce_stats         per-row M, Z; alpha'[row][tile] (proven)
//   pv_mma (TRANSPOSED)  E^T[n][i] = vT @ P^T: A = vT (L2-hot, 4MB/batch),
//                        B = probs (read ONCE, alpha' on B-fragments),
//                        accumulator lands in output orientation.
// R13 lesson: pv was A-traffic bound (4x re-read = 512 MB); transpose the
//   GEMM so the big operand is read once and the small one is L2-resident.
// ---------------------------------------------------------------------------

constexpr int kHW  = 4096;
constexpr int kC   = 512;
constexpr int kTok = 4 * kHW;   // 16384

__device__ __half g_qs  [kTok * 128];                   // 4 MB q split [hi|lo]
__device__ __half g_ks  [kTok * 128];                   // 4 MB k split [hi|lo]
__device__ __half g_sh  [(size_t)4 * kHW * kHW];        // 128 MB fp16 e-values
__device__ float  g_mt  [(size_t)kTok * 32];            // 2 MB per-(row,tile) max
__device__ float  g_st  [(size_t)kTok * 32];            // 2 MB per-(row,tile) sum
__device__ __half g_scale[(size_t)kTok * 32];           // 1 MB alpha'
__device__ __half g_vT  [(size_t)4 * kC * kHW];         // 16 MB vT[b][n][j]
__device__ __half g_xh  [(size_t)kTok * kC];            // 16 MB x hi fp16
__device__ __half g_xl  [(size_t)kTok * kC];            // 16 MB x lo fp16
__device__ __half g_w12h[128 * kC];                     // 128 KB W12^T hi
__device__ __half g_w12l[128 * kC];                     // 128 KB W12^T lo
__device__ __half g_w3T [kC * kC];                      // 512 KB W3^T fp16

// ============================ PTX helpers ==================================
__device__ __forceinline__ uint32_t smem_u32(const void* p) {
    uint32_t a;
    asm("{ .reg .u64 t; cvta.to.shared.u64 t, %1; cvt.u32.u64 %0, t; }"
        : "=r"(a) : "l"(p));
    return a;
}
__device__ __forceinline__ void ldmx4(uint32_t& r0, uint32_t& r1, uint32_t& r2,
                                      uint32_t& r3, uint32_t a) {
    asm volatile("ldmatrix.sync.aligned.m8n8.x4.shared.b16 {%0,%1,%2,%3}, [%4];"
                 : "=r"(r0), "=r"(r1), "=r"(r2), "=r"(r3) : "r"(a));
}
__device__ __forceinline__ void mma16816(float* c, const uint32_t* a,
                                         const uint32_t* b) {
    asm volatile(
        "mma.sync.aligned.m16n8k16.row.col.f32.f16.f16.f32 "
        "{%0,%1,%2,%3}, {%4,%5,%6,%7}, {%8,%9}, {%0,%1,%2,%3};"
        : "+f"(c[0]), "+f"(c[1]), "+f"(c[2]), "+f"(c[3])
        : "r"(a[0]), "r"(a[1]), "r"(a[2]), "r"(a[3]), "r"(b[0]), "r"(b[1]));
}
#define CP16(sm, gp) \
    asm volatile("cp.async.cg.shared.global [%0], [%1], 16;" :: "r"(sm), "l"(gp))
#define CP_COMMIT() asm volatile("cp.async.commit_group;" ::: "memory")
#define CP_WAIT(n)  asm volatile("cp.async.wait_group %0;" :: "n"(n) : "memory")

__device__ __forceinline__ float exp2f_fast(float f) {
    f = fmaxf(f, -126.f);
    float n = floorf(f);
    float r = f - n;
    float p = 1.5252734e-5f;
    p = fmaf(p, r, 1.5403530e-4f);
    p = fmaf(p, r, 1.3333558e-3f);
    p = fmaf(p, r, 9.6181291e-3f);
    p = fmaf(p, r, 5.5504109e-2f);
    p = fmaf(p, r, 2.4022651e-1f);
    p = fmaf(p, r, 6.9314718e-1f);
    p = fmaf(p, r, 1.0f);
    return p * __int_as_float((((int)n) + 127) << 23);
}
constexpr float LOG2E = 1.4426950408889634f;

// ============ HMMA NT skeleton constants ===================================
constexpr int PV_LDA   = 72;                        // halves, padded
constexpr int PV_ABUF  = 128 * PV_LDA * 2;          // 18432 B
constexpr int PV_SMEM  = 4 * PV_ABUF;               // 73728 B
constexpr int PV2_SMEM = PV_SMEM + 128 * 33 * 4;    // + alpha_s = 90624 B

// ================== prep_all: merged elementwise prep ======================
__global__ __launch_bounds__(256) void prep_all(const float* __restrict__ x,
                                                const float* __restrict__ W1,
                                                const float* __restrict__ W2,
                                                const float* __restrict__ W3) {
    __shared__ float t[32][33];
    const int blk = blockIdx.x;
    if (blk < 8192) {
        int idx = blk * 256 + threadIdx.x;
        float4 v = *(const float4*)(x + (size_t)idx * 4);
        __half h0 = __float2half_rn(v.x), h1 = __float2half_rn(v.y);
        __half h2 = __float2half_rn(v.z), h3 = __float2half_rn(v.w);
        __half2* dh = (__half2*)(g_xh + (size_t)idx * 4);
        dh[0] = __halves2half2(h0, h1);
        dh[1] = __halves2half2(h2, h3);
        __half2* dl = (__half2*)(g_xl + (size_t)idx * 4);
        dl[0] = __floats2half2_rn(v.x - __half2float(h0), v.y - __half2float(h1));
        dl[1] = __floats2half2_rn(v.z - __half2float(h2), v.w - __half2float(h3));
    } else if (blk < 8448) {
        int idx = (blk - 8192) * 256 + threadIdx.x;
        int n = idx >> 9, k = idx & 511;
        float v = (n < 64) ? W1[k * 64 + n] : W2[k * 64 + (n - 64)];
        __half hi = __float2half_rn(v);
        __half lo = __float2half_rn(v - __half2float(hi));
        g_w12h[idx] = hi;
        g_w12l[idx] = lo;
    } else {
        int id = blk - 8448;
        const int n0 = (id & 15) * 32;
        const int k0 = (id >> 4) * 32;
        const int tx = threadIdx.x & 31, ty = threadIdx.x >> 5;
        #pragma unroll
        for (int j = 0; j < 4; j++) {
            int kk = ty + j * 8;
            t[kk][tx] = W3[(size_t)(k0 + kk) * kC + n0 + tx];
        }
        __syncthreads();
        #pragma unroll
        for (int j = 0; j < 4; j++) {
            int nn = ty + j * 8;
            g_w3T[(size_t)(n0 + nn) * kC + k0 + tx] = __float2half_rn(t[tx][nn]);
        }
    }
}

// ===== HMMA: q|k projection via 3-term split (proven), emits hi/lo =========
__global__ void __launch_bounds__(256, 2) qkproj_mma() {
    extern __shared__ char smem[];
    const uint32_t sb  = smem_u32(smem);
    const int tid  = threadIdx.x;
    const int lane = tid & 31, wid = tid >> 5;
    const int wm = (wid & 1) * 64, wn = (wid >> 1) * 32;
    const int m0 = blockIdx.y * 128;

    const uint32_t sA[2] = {sb, sb + PV_ABUF};
    const uint32_t sB[2] = {sb + 2 * PV_ABUF, sb + 3 * PV_ABUF};

    const int ldrow  = tid >> 3;
    const int ldslot = (tid & 7) * 8;

    float acc[4][4][4];
    #pragma unroll
    for (int i = 0; i < 4; i++)
        #pragma unroll
        for (int j = 0; j < 4; j++)
            #pragma unroll
            for (int r = 0; r < 4; r++) acc[i][j][r] = 0.f;

    const int aRow = wm + (lane & 15);
    const int aCol = (lane >> 4) * 8;
    const int bRow = wn + ((lane >> 4) << 3) + (lane & 7);
    const int bCol = ((lane >> 3) & 1) * 8;

#define QK_PREFETCH(i, buf) do {                                               \
    const int term = (i) >> 3, kc = (i) & 7;                                   \
    const __half* Ap = ((term == 1) ? g_xl : g_xh) + (size_t)m0 * kC + kc * 64; \
    const __half* Bp = ((term == 2) ? g_w12l : g_w12h) + kc * 64;              \
    _Pragma("unroll") for (int q = 0; q < 4; q++) {                            \
        int r = q * 32 + ldrow;                                                \
        CP16(sA[buf] + (r * PV_LDA + ldslot) * 2, Ap + (size_t)r * kC + ldslot); \
        CP16(sB[buf] + (r * PV_LDA + ldslot) * 2, Bp + (size_t)r * kC + ldslot); \
    }                                                                          \
    CP_COMMIT();                                                               \
} while (0)

    QK_PREFETCH(0, 0);
    for (int i = 0; i < 24; i++) {
        const int buf = i & 1;
        if (i < 23) { QK_PREFETCH(i + 1, buf ^ 1); CP_WAIT(1); }
        else        { CP_WAIT(0); }
        __syncthreads();

        #pragma unroll
        for (int ks = 0; ks < 4; ks++) {
            uint32_t af[4][4], bf[4][2];
            #pragma unroll
            for (int mt = 0; mt < 4; mt++)
                ldmx4(af[mt][0], af[mt][1], af[mt][2], af[mt][3],
                      sA[buf] + ((aRow + mt * 16) * PV_LDA + aCol + ks * 16) * 2);
            #pragma unroll
            for (int np = 0; np < 2; np++)
                ldmx4(bf[np * 2][0], bf[np * 2][1], bf[np * 2 + 1][0], bf[np * 2 + 1][1],
                      sB[buf] + ((bRow + np * 16) * PV_LDA + bCol + ks * 16) * 2);
            #pragma unroll
            for (int mt = 0; mt < 4; mt++)
                #pragma unroll
                for (int nt = 0; nt < 4; nt++)
                    mma16816(acc[mt][nt], af[mt], bf[nt]);
        }
        __syncthreads();
    }
#undef QK_PREFETCH

    float* stage = (float*)smem;          // [128][132]
    #pragma unroll
    for (int mt = 0; mt < 4; mt++)
        #pragma unroll
        for (int nt = 0; nt < 4; nt++)
            #pragma unroll
            for (int r = 0; r < 4; r++) {
                int m = wm + mt * 16 + (lane >> 2) + ((r >= 2) ? 8 : 0);
                int n = wn + nt * 8 + (lane & 3) * 2 + (r & 1);
                stage[m * 132 + n] = acc[mt][nt][r];
            }
    __syncthreads();

    #pragma unroll
    for (int q = 0; q < 16; q++) {
        int idx = tid + q * 256;
        int t   = idx >> 5;
        int c4  = (idx & 31) << 2;
        const float* sp = stage + t * 132 + c4;
        __half hi[4], lo[4];
        #pragma unroll
        for (int j = 0; j < 4; j++) {
            hi[j] = __float2half_rn(sp[j]);
            lo[j] = __float2half_rn(sp[j] - __half2float(hi[j]));
        }
        __half* base = (c4 < 64) ? (g_qs + (size_t)(m0 + t) * 128 + c4)
                                 : (g_ks + (size_t)(m0 + t) * 128 + (c4 - 64));
        *(uint2*)base        = *(uint2*)hi;
        *(uint2*)(base + 64) = *(uint2*)lo;
    }
}

// ======= MERGED: exp_tiles (blocks 0..4095) + vproj (blocks 4096..4607) ====
__global__ void __launch_bounds__(256, 2) exp_vproj() {
    extern __shared__ char smem[];
    const uint32_t sb  = smem_u32(smem);
    const int tid  = threadIdx.x;
    const int lane = tid & 31, wid = tid >> 5;
    const int wm = (wid & 1) * 64, wn = (wid >> 1) * 32;

    const uint32_t sA[2] = {sb, sb + PV_ABUF};
    const uint32_t sB[2] = {sb + 2 * PV_ABUF, sb + 3 * PV_ABUF};
    const int ldrow  = tid >> 3;
    const int ldslot = (tid & 7) * 8;

    const int aRow = wm + (lane & 15);
    const int aCol = (lane >> 4) * 8;
    const int bRow = wn + ((lane >> 4) << 3) + (lane & 7);
    const int bCol = ((lane >> 3) & 1) * 8;

    float acc[4][4][4];
    #pragma unroll
    for (int i = 0; i < 4; i++)
        #pragma unroll
        for (int j = 0; j < 4; j++)
            #pragma unroll
            for (int r = 0; r < 4; r++) acc[i][j][r] = 0.f;

    const int id = blockIdx.x;

    if (id < 4096) {
        const int bz = id >> 10;
        const int m0 = ((id >> 5) & 31) * 128;
        const int n0 = (id & 31) * 128;

        const __half* Asrc = g_qs + ((size_t)bz * kHW + m0) * 128;
        const __half* Bsrc = g_ks + ((size_t)bz * kHW + n0) * 128;

        const int AOFF[3] = {0, 64, 0};
        const int BOFF[3] = {0, 0, 64};

        #pragma unroll
        for (int q = 0; q < 4; q++) {
            int r = q * 32 + ldrow;
            CP16(sA[0] + (r * PV_LDA + ldslot) * 2, Asrc + (size_t)r * 128 + AOFF[0] + ldslot);
            CP16(sB[0] + (r * PV_LDA + ldslot) * 2, Bsrc + (size_t)r * 128 + BOFF[0] + ldslot);
        }
        CP_COMMIT();

        for (int i = 0; i < 3; i++) {
            const int buf = i & 1;
            if (i < 2) {
                #pragma unroll
                for (int q = 0; q < 4; q++) {
                    int r = q * 32 + ldrow;
                    CP16(sA[buf ^ 1] + (r * PV_LDA + ldslot) * 2,
                         Asrc + (size_t)r * 128 + AOFF[i + 1] + ldslot);
                    CP16(sB[buf ^ 1] + (r * PV_LDA + ldslot) * 2,
                         Bsrc + (size_t)r * 128 + BOFF[i + 1] + ldslot);
                }
                CP_COMMIT();
                CP_WAIT(1);
            } else {
                CP_WAIT(0);
            }
            __syncthreads();

            #pragma unroll
            for (int ks = 0; ks < 4; ks++) {
                uint32_t af[4][4], bf[4][2];
                #pragma unroll
                for (int mt = 0; mt < 4; mt++)
                    ldmx4(af[mt][0], af[mt][1], af[mt][2], af[mt][3],
                          sA[buf] + ((aRow + mt * 16) * PV_LDA + aCol + ks * 16) * 2);
                #pragma unroll
                for (int np = 0; np < 2; np++)
                    ldmx4(bf[np * 2][0], bf[np * 2][1], bf[np * 2 + 1][0], bf[np * 2 + 1][1],
                          sB[buf] + ((bRow + np * 16) * PV_LDA + bCol + ks * 16) * 2);
                #pragma unroll
                for (int mt = 0; mt < 4; mt++)
                    #pragma unroll
                    for (int nt = 0; nt < 4; nt++)
                        mma16816(acc[mt][nt], af[mt], bf[nt]);
            }
            __syncthreads();
        }

        __half* stageh = (__half*)smem;                        // [128][136]
        float*  pmax   = (float*)(smem + 128 * 136 * 2);       // [128][4]
        float*  psum   = (float*)(smem + 128 * 136 * 2 + 2048);// [128][4]
        float*  rowm2  = (float*)(smem + 128 * 136 * 2 + 4096);// [128]
        const int cg = wid >> 1;

        #pragma unroll
        for (int mt = 0; mt < 4; mt++) {
            float ma = -1e30f, mb = -1e30f;
            #pragma unroll
            for (int nt = 0; nt < 4; nt++) {
                ma = fmaxf(ma, fmaxf(acc[mt][nt][0], acc[mt][nt][1]));
                mb = fmaxf(mb, fmaxf(acc[mt][nt][2], acc[mt][nt][3]));
            }
            ma = fmaxf(ma, __shfl_xor_sync(0xffffffffu, ma, 1));
            ma = fmaxf(ma, __shfl_xor_sync(0xffffffffu, ma, 2));
            mb = fmaxf(mb, __shfl_xor_sync(0xffffffffu, mb, 1));
            mb = fmaxf(mb, __shfl_xor_sync(0xffffffffu, mb, 2));
            if ((lane & 3) == 0) {
                int ra = wm + mt * 16 + (lane >> 2);
                pmax[ra * 4 + cg]       = ma;
                pmax[(ra + 8) * 4 + cg] = mb;
            }
        }
        __syncthreads();
        if (tid < 128) {
            float m = fmaxf(fmaxf(pmax[tid * 4], pmax[tid * 4 + 1]),
                            fmaxf(pmax[tid * 4 + 2], pmax[tid * 4 + 3]));
            rowm2[tid] = m * LOG2E;
        }
        __syncthreads();

        #pragma unroll
        for (int mt = 0; mt < 4; mt++) {
            int ra = wm + mt * 16 + (lane >> 2);
            float m2a = rowm2[ra], m2b = rowm2[ra + 8];
            float sa = 0.f, sb2 = 0.f;
            #pragma unroll
            for (int nt = 0; nt < 4; nt++) {
                int col = wn + nt * 8 + (lane & 3) * 2;
                float e0 = exp2f_fast(fmaf(acc[mt][nt][0], LOG2E, -m2a));
                float e1 = exp2f_fast(fmaf(acc[mt][nt][1], LOG2E, -m2a));
                float e2 = exp2f_fast(fmaf(acc[mt][nt][2], LOG2E, -m2b));
                float e3 = exp2f_fast(fmaf(acc[mt][nt][3], LOG2E, -m2b));
                sa  += e0 + e1;
                sb2 += e2 + e3;
                *(__half2*)(stageh + ra * 136 + col)       = __floats2half2_rn(e0, e1);
                *(__half2*)(stageh + (ra + 8) * 136 + col) = __floats2half2_rn(e2, e3);
            }
            sa  += __shfl_xor_sync(0xffffffffu, sa, 1);
            sa  += __shfl_xor_sync(0xffffffffu, sa, 2);
            sb2 += __shfl_xor_sync(0xffffffffu, sb2, 1);
            sb2 += __shfl_xor_sync(0xffffffffu, sb2, 2);
            if ((lane & 3) == 0) {
                psum[ra * 4 + cg]       = sa;
                psum[(ra + 8) * 4 + cg] = sb2;
            }
        }
        __syncthreads();

        if (tid < 128) {
            float s = psum[tid * 4] + psum[tid * 4 + 1] + psum[tid * 4 + 2] + psum[tid * 4 + 3];
            size_t ridx = ((size_t)bz * kHW + m0 + tid) * 32 + (n0 >> 7);
            g_mt[ridx] = rowm2[tid];
            g_st[ridx] = s;
        }

        __half* Pp = g_sh + (size_t)bz * kHW * kHW;
        #pragma unroll
        for (int q = 0; q < 8; q++) {
            int idx = tid + q * 256;
            int r = idx >> 4, c = (idx & 15) * 8;
            *(uint4*)(Pp + (size_t)(m0 + r) * kHW + n0 + c) = *(uint4*)(stageh + r * 136 + c);
        }
    } else {
        const int id2 = id - 4096;
        const int n0 = (id2 & 3) * 128;
        const int m0 = (id2 >> 2) * 128;

        const __half* Asrc = g_xh + (size_t)m0 * kC;
        const __half* Bsrc = g_w3T + (size_t)n0 * kC;

        #pragma unroll
        for (int q = 0; q < 4; q++) {
            int r = q * 32 + ldrow;
            CP16(sA[0] + (r * PV_LDA + ldslot) * 2, Asrc + (size_t)r * kC + ldslot);
            CP16(sB[0] + (r * PV_LDA + ldslot) * 2, Bsrc + (size_t)r * kC + ldslot);
        }
        CP_COMMIT();

        for (int i = 0; i < 8; i++) {
            const int buf = i & 1;
            if (i < 7) {
                const int k0 = (i + 1) * 64;
                #pragma unroll
                for (int q = 0; q < 4; q++) {
                    int r = q * 32 + ldrow;
                    CP16(sA[buf ^ 1] + (r * PV_LDA + ldslot) * 2,
                         Asrc + (size_t)r * kC + k0 + ldslot);
                    CP16(sB[buf ^ 1] + (r * PV_LDA + ldslot) * 2,
                         Bsrc + (size_t)r * kC + k0 + ldslot);
                }
                CP_COMMIT();
                CP_WAIT(1);
            } else {
                CP_WAIT(0);
            }
            __syncthreads();

            #pragma unroll
            for (int ks = 0; ks < 4; ks++) {
                uint32_t af[4][4], bf[4][2];
                #pragma unroll
                for (int mt = 0; mt < 4; mt++)
                    ldmx4(af[mt][0], af[mt][1], af[mt][2], af[mt][3],
                          sA[buf] + ((aRow + mt * 16) * PV_LDA + aCol + ks * 16) * 2);
                #pragma unroll
                for (int np = 0; np < 2; np++)
                    ldmx4(bf[np * 2][0], bf[np * 2][1], bf[np * 2 + 1][0], bf[np * 2 + 1][1],
                          sB[buf] + ((bRow + np * 16) * PV_LDA + bCol + ks * 16) * 2);
                #pragma unroll
                for (int mt = 0; mt < 4; mt++)
                    #pragma unroll
                    for (int nt = 0; nt < 4; nt++)
                        mma16816(acc[mt][nt], af[mt], bf[nt]);
            }
            __syncthreads();
        }

        __half* stage = (__half*)smem;        // [128][136]
        constexpr int SLD = 136;
        #pragma unroll
        for (int mt = 0; mt < 4; mt++)
            #pragma unroll
            for (int nt = 0; nt < 4; nt++)
                #pragma unroll
                for (int r = 0; r < 4; r++) {
                    int m = wm + mt * 16 + (lane >> 2) + ((r >= 2) ? 8 : 0);
                    int n = wn + nt * 8 + (lane & 3) * 2 + (r & 1);
                    stage[n * SLD + m] = __float2half_rn(acc[mt][nt][r]);
                }
        __syncthreads();

        const int bz = m0 >> 12;
        const int ml = m0 & 4095;
        #pragma unroll
        for (int q = 0; q < 8; q++) {
            int idx = tid + q * 256;
            int n   = idx >> 4;
            int m8  = (idx & 15) << 3;
            __half* dst = g_vT + ((size_t)bz * kC + n0 + n) * kHW + ml + m8;
            *(uint4*)dst = *(uint4*)(stage + n * SLD + m8);
        }
    }
}

// ===== per-row reduce: M = max m2_t, Z = sum s_t*2^(m2_t-M), alpha' fp16 ====
__global__ __launch_bounds__(256) void reduce_stats() {
    const int row  = blockIdx.x * 8 + (threadIdx.x >> 5);
    const int lane = threadIdx.x & 31;
    const size_t base = (size_t)row * 32;
    float m2 = g_mt[base + lane];
    float s  = g_st[base + lane];
    float M2 = m2;
    #pragma unroll
    for (int o = 16; o > 0; o >>= 1) M2 = fmaxf(M2, __shfl_xor_sync(0xffffffffu, M2, o));
    float a = exp2f_fast(m2 - M2);
    float z = s * a;
    #pragma unroll
    for (int o = 16; o > 0; o >>= 1) z += __shfl_xor_sync(0xffffffffu, z, o);
    g_scale[base + lane] = __float2half_rn(a / z);
}

// ===== pv_mma TRANSPOSED: E^T = vT @ P^T, alpha' on B fragments ============
// A = g_vT [channel][k] (L2-hot), B = g_sh [token i][k] (read once).
// acc[m=channel][n=token] -> output orientation directly.
// grid: x = token tile (32), y = channel tile (4), z = batch
__global__ void __launch_bounds__(256, 2)
pv_mma(const float* __restrict__ x, const float* __restrict__ gamma,
       float* __restrict__ out) {
    extern __shared__ char smem[];
    const uint32_t sb  = smem_u32(smem);
    const int tid  = threadIdx.x;
    const int lane = tid & 31, wid = tid >> 5;
    const int wm = (wid & 1) * 64, wn = (wid >> 1) * 32;
    const int i0 = blockIdx.x * 128;      // token tile (B rows / output cols)
    const int c0 = blockIdx.y * 128;      // channel tile (A rows / output rows)
    const int bz = blockIdx.z;

    const __half* Asrc = g_vT + ((size_t)bz * kC + c0) * kHW;
    const __half* Bsrc = g_sh + (size_t)bz * kHW * kHW + (size_t)i0 * kHW;

    const uint32_t sA[2] = {sb, sb + PV_ABUF};
    const uint32_t sB[2] = {sb + 2 * PV_ABUF, sb + 3 * PV_ABUF};
    float* alpha_s = (float*)(smem + 4 * PV_ABUF);   // [128][33] (token rows)

    const int ldrow  = tid >> 3;
    const int ldslot = (tid & 7) * 8;

    // alpha' for token rows i0..i0+127
    #pragma unroll
    for (int q = 0; q < 16; q++) {
        int idx = tid + q * 256;
        int r = idx >> 5, t = idx & 31;
        alpha_s[r * 33 + t] =
            __half2float(g_scale[((size_t)bz * kHW + i0 + r) * 32 + t]);
    }

    float acc[4][4][4];
    #pragma unroll
    for (int i = 0; i < 4; i++)
        #pragma unroll
        for (int j = 0; j < 4; j++)
            #pragma unroll
            for (int r = 0; r < 4; r++) acc[i][j][r] = 0.f;

    const int aRow = wm + (lane & 15);
    const int aCol = (lane >> 4) * 8;
    const int bRow = wn + ((lane >> 4) << 3) + (lane & 7);
    const int bCol = ((lane >> 3) & 1) * 8;

    #pragma unroll
    for (int q = 0; q < 4; q++) {
        int r = q * 32 + ldrow;
        CP16(sA[0] + (r * PV_LDA + ldslot) * 2, Asrc + (size_t)r * kHW + ldslot);
        CP16(sB[0] + (r * PV_LDA + ldslot) * 2, Bsrc + (size_t)r * kHW + ldslot);
    }
    CP_COMMIT();

    for (int i = 0; i < 64; i++) {
        const int buf = i & 1;
        if (i < 63) {
            const int k0 = (i + 1) * 64;
            #pragma unroll
            for (int q = 0; q < 4; q++) {
                int r = q * 32 + ldrow;
                CP16(sA[buf ^ 1] + (r * PV_LDA + ldslot) * 2,
                     Asrc + (size_t)r * kHW + k0 + ldslot);
                CP16(sB[buf ^ 1] + (r * PV_LDA + ldslot) * 2,
                     Bsrc + (size_t)r * kHW + k0 + ldslot);
            }
            CP_COMMIT();
            CP_WAIT(1);
        } else {
            CP_WAIT(0);
        }
        __syncthreads();

        // alpha' per B-fragment row: token rn = wn + nt*8 + (lane>>2)
        const int tile = i >> 1;
        __half2 hbv[4];
        #pragma unroll
        for (int nt = 0; nt < 4; nt++) {
            int rn = wn + nt * 8 + (lane >> 2);
            hbv[nt] = __half2half2(__float2half_rn(alpha_s[rn * 33 + tile]));
        }

        #pragma unroll
        for (int ks = 0; ks < 4; ks++) {
            uint32_t af[4][4], bf[4][2];
            #pragma unroll
            for (int mt = 0; mt < 4; mt++)
                ldmx4(af[mt][0], af[mt][1], af[mt][2], af[mt][3],
                      sA[buf] + ((aRow + mt * 16) * PV_LDA + aCol + ks * 16) * 2);
            #pragma unroll
            for (int np = 0; np < 2; np++)
                ldmx4(bf[np * 2][0], bf[np * 2][1], bf[np * 2 + 1][0], bf[np * 2 + 1][1],
                      sB[buf] + ((bRow + np * 16) * PV_LDA + bCol + ks * 16) * 2);
            #pragma unroll
            for (int nt = 0; nt < 4; nt++) {
                *(__half2*)&bf[nt][0] = __hmul2(*(__half2*)&bf[nt][0], hbv[nt]);
                *(__half2*)&bf[nt][1] = __hmul2(*(__half2*)&bf[nt][1], hbv[nt]);
            }
            #pragma unroll
            for (int mt = 0; mt < 4; mt++)
                #pragma unroll
                for (int nt = 0; nt < 4; nt++)
                    mma16816(acc[mt][nt], af[mt], bf[nt]);
        }
        __syncthreads();
    }

    // stage [m=channel][n=token] fp32 -> fused coalesced output (tokens contig)
    float* stage = (float*)smem;          // [128][132]
    #pragma unroll
    for (int mt = 0; mt < 4; mt++)
        #pragma unroll
        for (int nt = 0; nt < 4; nt++)
            #pragma unroll
            for (int r = 0; r < 4; r++) {
                int m = wm + mt * 16 + (lane >> 2) + ((r >= 2) ? 8 : 0);
                int n = wn + nt * 8 + (lane & 3) * 2 + (r & 1);
                stage[m * 132 + n] = acc[mt][nt][r];
            }
    __syncthreads();

    const float g = __ldg(gamma);
    const size_t obofs = (size_t)bz * kHW * kC;
    #pragma unroll
    for (int q = 0; q < 16; q++) {
        int idx = tid + q * 256;
        int m   = idx >> 5;               // channel within tile
        int n4  = (idx & 31) << 2;        // token group
        size_t o = obofs + (size_t)(c0 + m) * kHW + i0 + n4;
        float4 xv = *(const float4*)(x + o);
        const float* sp = stage + m * 132 + n4;
        *(float4*)(out + o) = make_float4(fmaf(g, sp[0], xv.x), fmaf(g, sp[1], xv.y),
                                          fmaf(g, sp[2], xv.z), fmaf(g, sp[3], xv.w));
    }
}

// ---------------------------------------------------------------------------
extern "C" void kernel_launch(void* const* d_in, const int* in_sizes, int n_in,
                              void* d_out, int out_size) {
    const float* x     = (const float*)d_in[0];
    const float* W1    = (const float*)d_in[1];
    const float* W2    = (const float*)d_in[2];
    const float* W3    = (const float*)d_in[3];
    const float* gamma = (const float*)d_in[4];
    float* out = (float*)d_out;

    cudaFuncSetAttribute(pv_mma, cudaFuncAttributeMaxDynamicSharedMemorySize, PV2_SMEM);
    cudaFuncSetAttribute(qkproj_mma, cudaFuncAttributeMaxDynamicSharedMemorySize, PV_SMEM);
    cudaFuncSetAttribute(exp_vproj, cudaFuncAttributeMaxDynamicSharedMemorySize, PV_SMEM);

    prep_all<<<8704, 256>>>(x, W1, W2, W3);               // merged prep
    qkproj_mma<<<dim3(1, 128), 256, PV_SMEM>>>();         // q,k hi/lo (proven)
    exp_vproj<<<4608, 256, PV_SMEM>>>();                  // exp_tiles || vproj
    reduce_stats<<<2048, 256>>>();                        // M, Z, alpha'
    pv_mma<<<dim3(32, 4, 4), 256, PV2_SMEM>>>(x, gamma, out);
}

// round 15
// speedup vs baseline: 1.1650x; 1.0061x over previous
#include <cuda_runtime.h>
#include <cuda_fp16.h>
#include <cstdint>

// ---------------------------------------------------------------------------
// PositionAttentionModule: B=4, HW=4096, C=512, Cr=64
//   prep_all             x->hi/lo fp16, W12^T hi/lo, W3^T fp16 (merged)
//   qkproj_mma           3-term split HMMA, 64-row tiles x 256 CTAs
//   exp_vproj            exp_tiles (QK^T + tile softmax -> e fp16) || vproj
//   pv_mma (TRANSPOSED)  E^T = vT @ P^T with alpha' computed IN-PROLOGUE
//                        from g_mt/g_st (reduce_stats kernel eliminated)
// R14 lessons: pv ~50% of mma ceiling (issue-bound); qkproj latency-bound at
//   1 underfilled wave -> double CTA parallelism; kill small-kernel launches.
// ---------------------------------------------------------------------------

constexpr int kHW  = 4096;
constexpr int kC   = 512;
constexpr int kTok = 4 * kHW;   // 16384

__device__ __half g_qs  [kTok * 128];                   // 4 MB q split [hi|lo]
__device__ __half g_ks  [kTok * 128];                   // 4 MB k split [hi|lo]
__device__ __half g_sh  [(size_t)4 * kHW * kHW];        // 128 MB fp16 e-values
__device__ float  g_mt  [(size_t)kTok * 32];            // 2 MB per-(row,tile) max
__device__ float  g_st  [(size_t)kTok * 32];            // 2 MB per-(row,tile) sum
__device__ __half g_vT  [(size_t)4 * kC * kHW];         // 16 MB vT[b][n][j]
__device__ __half g_xh  [(size_t)kTok * kC];            // 16 MB x hi fp16
__device__ __half g_xl  [(size_t)kTok * kC];            // 16 MB x lo fp16
__device__ __half g_w12h[128 * kC];                     // 128 KB W12^T hi
__device__ __half g_w12l[128 * kC];                     // 128 KB W12^T lo
__device__ __half g_w3T [kC * kC];                      // 512 KB W3^T fp16

// ============================ PTX helpers ==================================
__device__ __forceinline__ uint32_t smem_u32(const void* p) {
    uint32_t a;
    asm("{ .reg .u64 t; cvta.to.shared.u64 t, %1; cvt.u32.u64 %0, t; }"
        : "=r"(a) : "l"(p));
    return a;
}
__device__ __forceinline__ void ldmx4(uint32_t& r0, uint32_t& r1, uint32_t& r2,
                                      uint32_t& r3, uint32_t a) {
    asm volatile("ldmatrix.sync.aligned.m8n8.x4.shared.b16 {%0,%1,%2,%3}, [%4];"
                 : "=r"(r0), "=r"(r1), "=r"(r2), "=r"(r3) : "r"(a));
}
__device__ __forceinline__ void mma16816(float* c, const uint32_t* a,
                                         const uint32_t* b) {
    asm volatile(
        "mma.sync.aligned.m16n8k16.row.col.f32.f16.f16.f32 "
        "{%0,%1,%2,%3}, {%4,%5,%6,%7}, {%8,%9}, {%0,%1,%2,%3};"
        : "+f"(c[0]), "+f"(c[1]), "+f"(c[2]), "+f"(c[3])
        : "r"(a[0]), "r"(a[1]), "r"(a[2]), "r"(a[3]), "r"(b[0]), "r"(b[1]));
}
#define CP16(sm, gp) \
    asm volatile("cp.async.cg.shared.global [%0], [%1], 16;" :: "r"(sm), "l"(gp))
#define CP_COMMIT() asm volatile("cp.async.commit_group;" ::: "memory")
#define CP_WAIT(n)  asm volatile("cp.async.wait_group %0;" :: "n"(n) : "memory")

__device__ __forceinline__ float exp2f_fast(float f) {
    f = fmaxf(f, -126.f);
    float n = floorf(f);
    float r = f - n;
    float p = 1.5252734e-5f;
    p = fmaf(p, r, 1.5403530e-4f);
    p = fmaf(p, r, 1.3333558e-3f);
    p = fmaf(p, r, 9.6181291e-3f);
    p = fmaf(p, r, 5.5504109e-2f);
    p = fmaf(p, r, 2.4022651e-1f);
    p = fmaf(p, r, 6.9314718e-1f);
    p = fmaf(p, r, 1.0f);
    return p * __int_as_float((((int)n) + 127) << 23);
}
constexpr float LOG2E = 1.4426950408889634f;

// ============ HMMA NT skeleton constants ===================================
constexpr int PV_LDA   = 72;                        // halves, padded
constexpr int PV_ABUF  = 128 * PV_LDA * 2;          // 18432 B
constexpr int PV_SMEM  = 4 * PV_ABUF;               // 73728 B
constexpr int PV2_SMEM = PV_SMEM + 128 * 33 * 4;    // + alpha_s = 90624 B

// ================== prep_all: merged elementwise prep ======================
__global__ __launch_bounds__(256) void prep_all(const float* __restrict__ x,
                                                const float* __restrict__ W1,
                                                const float* __restrict__ W2,
                                                const float* __restrict__ W3) {
    __shared__ float t[32][33];
    const int blk = blockIdx.x;
    if (blk < 8192) {
        int idx = blk * 256 + threadIdx.x;
        float4 v = *(const float4*)(x + (size_t)idx * 4);
        __half h0 = __float2half_rn(v.x), h1 = __float2half_rn(v.y);
        __half h2 = __float2half_rn(v.z), h3 = __float2half_rn(v.w);
        __half2* dh = (__half2*)(g_xh + (size_t)idx * 4);
        dh[0] = __halves2half2(h0, h1);
        dh[1] = __halves2half2(h2, h3);
        __half2* dl = (__half2*)(g_xl + (size_t)idx * 4);
        dl[0] = __floats2half2_rn(v.x - __half2float(h0), v.y - __half2float(h1));
        dl[1] = __floats2half2_rn(v.z - __half2float(h2), v.w - __half2float(h3));
    } else if (blk < 8448) {
        int idx = (blk - 8192) * 256 + threadIdx.x;
        int n = idx >> 9, k = idx & 511;
        float v = (n < 64) ? W1[k * 64 + n] : W2[k * 64 + (n - 64)];
        __half hi = __float2half_rn(v);
        __half lo = __float2half_rn(v - __half2float(hi));
        g_w12h[idx] = hi;
        g_w12l[idx] = lo;
    } else {
        int id = blk - 8448;
        const int n0 = (id & 15) * 32;
        const int k0 = (id >> 4) * 32;
        const int tx = threadIdx.x & 31, ty = threadIdx.x >> 5;
        #pragma unroll
        for (int j = 0; j < 4; j++) {
            int kk = ty + j * 8;
            t[kk][tx] = W3[(size_t)(k0 + kk) * kC + n0 + tx];
        }
        __syncthreads();
        #pragma unroll
        for (int j = 0; j < 4; j++) {
            int nn = ty + j * 8;
            g_w3T[(size_t)(n0 + nn) * kC + k0 + tx] = __float2half_rn(t[tx][nn]);
        }
    }
}

// ===== HMMA: q|k projection, 3-term split, 64-row tiles (256 CTAs) =========
__global__ void __launch_bounds__(256, 2) qkproj_mma() {
    extern __shared__ char smem[];
    const uint32_t sb  = smem_u32(smem);
    const int tid  = threadIdx.x;
    const int lane = tid & 31, wid = tid >> 5;
    const int wm = (wid & 1) * 32, wn = (wid >> 1) * 32;
    const int m0 = blockIdx.y * 64;

    const uint32_t sA[2] = {sb, sb + PV_ABUF};
    const uint32_t sB[2] = {sb + 2 * PV_ABUF, sb + 3 * PV_ABUF};

    const int ldrow  = tid >> 3;
    const int ldslot = (tid & 7) * 8;

    float acc[2][4][4];
    #pragma unroll
    for (int i = 0; i < 2; i++)
        #pragma unroll
        for (int j = 0; j < 4; j++)
            #pragma unroll
            for (int r = 0; r < 4; r++) acc[i][j][r] = 0.f;

    const int aRow = wm + (lane & 15);
    const int aCol = (lane >> 4) * 8;
    const int bRow = wn + ((lane >> 4) << 3) + (lane & 7);
    const int bCol = ((lane >> 3) & 1) * 8;

#define QK_PREFETCH(i, buf) do {                                               \
    const int term = (i) >> 3, kc = (i) & 7;                                   \
    const __half* Ap = ((term == 1) ? g_xl : g_xh) + (size_t)m0 * kC + kc * 64; \
    const __half* Bp = ((term == 2) ? g_w12l : g_w12h) + kc * 64;              \
    _Pragma("unroll") for (int q = 0; q < 2; q++) {                            \
        int r = q * 32 + ldrow;                                                \
        CP16(sA[buf] + (r * PV_LDA + ldslot) * 2, Ap + (size_t)r * kC + ldslot); \
    }                                                                          \
    _Pragma("unroll") for (int q = 0; q < 4; q++) {                            \
        int r = q * 32 + ldrow;                                                \
        CP16(sB[buf] + (r * PV_LDA + ldslot) * 2, Bp + (size_t)r * kC + ldslot); \
    }                                                                          \
    CP_COMMIT();                                                               \
} while (0)

    QK_PREFETCH(0, 0);
    for (int i = 0; i < 24; i++) {
        const int buf = i & 1;
        if (i < 23) { QK_PREFETCH(i + 1, buf ^ 1); CP_WAIT(1); }
        else        { CP_WAIT(0); }
        __syncthreads();

        #pragma unroll
        for (int ks = 0; ks < 4; ks++) {
            uint32_t af[2][4], bf[4][2];
            #pragma unroll
            for (int mt = 0; mt < 2; mt++)
                ldmx4(af[mt][0], af[mt][1], af[mt][2], af[mt][3],
                      sA[buf] + ((aRow + mt * 16) * PV_LDA + aCol + ks * 16) * 2);
            #pragma unroll
            for (int np = 0; np < 2; np++)
                ldmx4(bf[np * 2][0], bf[np * 2][1], bf[np * 2 + 1][0], bf[np * 2 + 1][1],
                      sB[buf] + ((bRow + np * 16) * PV_LDA + bCol + ks * 16) * 2);
            #pragma unroll
            for (int mt = 0; mt < 2; mt++)
                #pragma unroll
                for (int nt = 0; nt < 4; nt++)
                    mma16816(acc[mt][nt], af[mt], bf[nt]);
        }
        __syncthreads();
    }
#undef QK_PREFETCH

    float* stage = (float*)smem;          // [64][132]
    #pragma unroll
    for (int mt = 0; mt < 2; mt++)
        #pragma unroll
        for (int nt = 0; nt < 4; nt++)
            #pragma unroll
            for (int r = 0; r < 4; r++) {
                int m = wm + mt * 16 + (lane >> 2) + ((r >= 2) ? 8 : 0);
                int n = wn + nt * 8 + (lane & 3) * 2 + (r & 1);
                stage[m * 132 + n] = acc[mt][nt][r];
            }
    __syncthreads();

    #pragma unroll
    for (int q = 0; q < 8; q++) {
        int idx = tid + q * 256;          // 0..2047
        int t   = idx >> 5;               // 0..63
        int c4  = (idx & 31) << 2;
        const float* sp = stage + t * 132 + c4;
        __half hi[4], lo[4];
        #pragma unroll
        for (int j = 0; j < 4; j++) {
            hi[j] = __float2half_rn(sp[j]);
            lo[j] = __float2half_rn(sp[j] - __half2float(hi[j]));
        }
        __half* base = (c4 < 64) ? (g_qs + (size_t)(m0 + t) * 128 + c4)
                                 : (g_ks + (size_t)(m0 + t) * 128 + (c4 - 64));
        *(uint2*)base        = *(uint2*)hi;
        *(uint2*)(base + 64) = *(uint2*)lo;
    }
}

// ======= MERGED: exp_tiles (blocks 0..4095) + vproj (blocks 4096..4607) ====
__global__ void __launch_bounds__(256, 2) exp_vproj() {
    extern __shared__ char smem[];
    const uint32_t sb  = smem_u32(smem);
    const int tid  = threadIdx.x;
    const int lane = tid & 31, wid = tid >> 5;
    const int wm = (wid & 1) * 64, wn = (wid >> 1) * 32;

    const uint32_t sA[2] = {sb, sb + PV_ABUF};
    const uint32_t sB[2] = {sb + 2 * PV_ABUF, sb + 3 * PV_ABUF};
    const int ldrow  = tid >> 3;
    const int ldslot = (tid & 7) * 8;

    const int aRow = wm + (lane & 15);
    const int aCol = (lane >> 4) * 8;
    const int bRow = wn + ((lane >> 4) << 3) + (lane & 7);
    const int bCol = ((lane >> 3) & 1) * 8;

    float acc[4][4][4];
    #pragma unroll
    for (int i = 0; i < 4; i++)
        #pragma unroll
        for (int j = 0; j < 4; j++)
            #pragma unroll
            for (int r = 0; r < 4; r++) acc[i][j][r] = 0.f;

    const int id = blockIdx.x;

    if (id < 4096) {
        const int bz = id >> 10;
        const int m0 = ((id >> 5) & 31) * 128;
        const int n0 = (id & 31) * 128;

        const __half* Asrc = g_qs + ((size_t)bz * kHW + m0) * 128;
        const __half* Bsrc = g_ks + ((size_t)bz * kHW + n0) * 128;

        const int AOFF[3] = {0, 64, 0};
        const int BOFF[3] = {0, 0, 64};

        #pragma unroll
        for (int q = 0; q < 4; q++) {
            int r = q * 32 + ldrow;
            CP16(sA[0] + (r * PV_LDA + ldslot) * 2, Asrc + (size_t)r * 128 + AOFF[0] + ldslot);
            CP16(sB[0] + (r * PV_LDA + ldslot) * 2, Bsrc + (size_t)r * 128 + BOFF[0] + ldslot);
        }
        CP_COMMIT();

        for (int i = 0; i < 3; i++) {
            const int buf = i & 1;
            if (i < 2) {
                #pragma unroll
                for (int q = 0; q < 4; q++) {
                    int r = q * 32 + ldrow;
                    CP16(sA[buf ^ 1] + (r * PV_LDA + ldslot) * 2,
                         Asrc + (size_t)r * 128 + AOFF[i + 1] + ldslot);
                    CP16(sB[buf ^ 1] + (r * PV_LDA + ldslot) * 2,
                         Bsrc + (size_t)r * 128 + BOFF[i + 1] + ldslot);
                }
                CP_COMMIT();
                CP_WAIT(1);
            } else {
                CP_WAIT(0);
            }
            __syncthreads();

            #pragma unroll
            for (int ks = 0; ks < 4; ks++) {
                uint32_t af[4][4], bf[4][2];
                #pragma unroll
                for (int mt = 0; mt < 4; mt++)
                    ldmx4(af[mt][0], af[mt][1], af[mt][2], af[mt][3],
                          sA[buf] + ((aRow + mt * 16) * PV_LDA + aCol + ks * 16) * 2);
                #pragma unroll
                for (int np = 0; np < 2; np++)
                    ldmx4(bf[np * 2][0], bf[np * 2][1], bf[np * 2 + 1][0], bf[np * 2 + 1][1],
                          sB[buf] + ((bRow + np * 16) * PV_LDA + bCol + ks * 16) * 2);
                #pragma unroll
                for (int mt = 0; mt < 4; mt++)
                    #pragma unroll
                    for (int nt = 0; nt < 4; nt++)
                        mma16816(acc[mt][nt], af[mt], bf[nt]);
            }
            __syncthreads();
        }

        __half* stageh = (__half*)smem;                        // [128][136]
        float*  pmax   = (float*)(smem + 128 * 136 * 2);       // [128][4]
        float*  psum   = (float*)(smem + 128 * 136 * 2 + 2048);// [128][4]
        float*  rowm2  = (float*)(smem + 128 * 136 * 2 + 4096);// [128]
        const int cg = wid >> 1;

        #pragma unroll
        for (int mt = 0; mt < 4; mt++) {
            float ma = -1e30f, mb = -1e30f;
            #pragma unroll
            for (int nt = 0; nt < 4; nt++) {
                ma = fmaxf(ma, fmaxf(acc[mt][nt][0], acc[mt][nt][1]));
                mb = fmaxf(mb, fmaxf(acc[mt][nt][2], acc[mt][nt][3]));
            }
            ma = fmaxf(ma, __shfl_xor_sync(0xffffffffu, ma, 1));
            ma = fmaxf(ma, __shfl_xor_sync(0xffffffffu, ma, 2));
            mb = fmaxf(mb, __shfl_xor_sync(0xffffffffu, mb, 1));
            mb = fmaxf(mb, __shfl_xor_sync(0xffffffffu, mb, 2));
            if ((lane & 3) == 0) {
                int ra = wm + mt * 16 + (lane >> 2);
                pmax[ra * 4 + cg]       = ma;
                pmax[(ra + 8) * 4 + cg] = mb;
            }
        }
        __syncthreads();
        if (tid < 128) {
            float m = fmaxf(fmaxf(pmax[tid * 4], pmax[tid * 4 + 1]),
                            fmaxf(pmax[tid * 4 + 2], pmax[tid * 4 + 3]));
            rowm2[tid] = m * LOG2E;
        }
        __syncthreads();

        #pragma unroll
        for (int mt = 0; mt < 4; mt++) {
            int ra = wm + mt * 16 + (lane >> 2);
            float m2a = rowm2[ra], m2b = rowm2[ra + 8];
            float sa = 0.f, sb2 = 0.f;
            #pragma unroll
            for (int nt = 0; nt < 4; nt++) {
                int col = wn + nt * 8 + (lane & 3) * 2;
                float e0 = exp2f_fast(fmaf(acc[mt][nt][0], LOG2E, -m2a));
                float e1 = exp2f_fast(fmaf(acc[mt][nt][1], LOG2E, -m2a));
                float e2 = exp2f_fast(fmaf(acc[mt][nt][2], LOG2E, -m2b));
                float e3 = exp2f_fast(fmaf(acc[mt][nt][3], LOG2E, -m2b));
                sa  += e0 + e1;
                sb2 += e2 + e3;
                *(__half2*)(stageh + ra * 136 + col)       = __floats2half2_rn(e0, e1);
                *(__half2*)(stageh + (ra + 8) * 136 + col) = __floats2half2_rn(e2, e3);
            }
            sa  += __shfl_xor_sync(0xffffffffu, sa, 1);
            sa  += __shfl_xor_sync(0xffffffffu, sa, 2);
            sb2 += __shfl_xor_sync(0xffffffffu, sb2, 1);
            sb2 += __shfl_xor_sync(0xffffffffu, sb2, 2);
            if ((lane & 3) == 0) {
                psum[ra * 4 + cg]       = sa;
                psum[(ra + 8) * 4 + cg] = sb2;
            }
        }
        __syncthreads();

        if (tid < 128) {
            float s = psum[tid * 4] + psum[tid * 4 + 1] + psum[tid * 4 + 2] + psum[tid * 4 + 3];
            size_t ridx = ((size_t)bz * kHW + m0 + tid) * 32 + (n0 >> 7);
            g_mt[ridx] = rowm2[tid];
            g_st[ridx] = s;
        }

        __half* Pp = g_sh + (size_t)bz * kHW * kHW;
        #pragma unroll
        for (int q = 0; q < 8; q++) {
            int idx = tid + q * 256;
            int r = idx >> 4, c = (idx & 15) * 8;
            *(uint4*)(Pp + (size_t)(m0 + r) * kHW + n0 + c) = *(uint4*)(stageh + r * 136 + c);
        }
    } else {
        const int id2 = id - 4096;
        const int n0 = (id2 & 3) * 128;
        const int m0 = (id2 >> 2) * 128;

        const __half* Asrc = g_xh + (size_t)m0 * kC;
        const __half* Bsrc = g_w3T + (size_t)n0 * kC;

        #pragma unroll
        for (int q = 0; q < 4; q++) {
            int r = q * 32 + ldrow;
            CP16(sA[0] + (r * PV_LDA + ldslot) * 2, Asrc + (size_t)r * kC + ldslot);
            CP16(sB[0] + (r * PV_LDA + ldslot) * 2, Bsrc + (size_t)r * kC + ldslot);
        }
        CP_COMMIT();

        for (int i = 0; i < 8; i++) {
            const int buf = i & 1;
            if (i < 7) {
                const int k0 = (i + 1) * 64;
                #pragma unroll
                for (int q = 0; q < 4; q++) {
                    int r = q * 32 + ldrow;
                    CP16(sA[buf ^ 1] + (r * PV_LDA + ldslot) * 2,
                         Asrc + (size_t)r * kC + k0 + ldslot);
                    CP16(sB[buf ^ 1] + (r * PV_LDA + ldslot) * 2,
                         Bsrc + (size_t)r * kC + k0 + ldslot);
                }
                CP_COMMIT();
                CP_WAIT(1);
            } else {
                CP_WAIT(0);
            }
            __syncthreads();

            #pragma unroll
            for (int ks = 0; ks < 4; ks++) {
                uint32_t af[4][4], bf[4][2];
                #pragma unroll
                for (int mt = 0; mt < 4; mt++)
                    ldmx4(af[mt][0], af[mt][1], af[mt][2], af[mt][3],
                          sA[buf] + ((aRow + mt * 16) * PV_LDA + aCol + ks * 16) * 2);
                #pragma unroll
                for (int np = 0; np < 2; np++)
                    ldmx4(bf[np * 2][0], bf[np * 2][1], bf[np * 2 + 1][0], bf[np * 2 + 1][1],
                          sB[buf] + ((bRow + np * 16) * PV_LDA + bCol + ks * 16) * 2);
                #pragma unroll
                for (int mt = 0; mt < 4; mt++)
                    #pragma unroll
                    for (int nt = 0; nt < 4; nt++)
                        mma16816(acc[mt][nt], af[mt], bf[nt]);
            }
            __syncthreads();
        }

        __half* stage = (__half*)smem;        // [128][136]
        constexpr int SLD = 136;
        #pragma unroll
        for (int mt = 0; mt < 4; mt++)
            #pragma unroll
            for (int nt = 0; nt < 4; nt++)
                #pragma unroll
                for (int r = 0; r < 4; r++) {
                    int m = wm + mt * 16 + (lane >> 2) + ((r >= 2) ? 8 : 0);
                    int n = wn + nt * 8 + (lane & 3) * 2 + (r & 1);
                    stage[n * SLD + m] = __float2half_rn(acc[mt][nt][r]);
                }
        __syncthreads();

        const int bz = m0 >> 12;
        const int ml = m0 & 4095;
        #pragma unroll
        for (int q = 0; q < 8; q++) {
            int idx = tid + q * 256;
            int n   = idx >> 4;
            int m8  = (idx & 15) << 3;
            __half* dst = g_vT + ((size_t)bz * kC + n0 + n) * kHW + ml + m8;
            *(uint4*)dst = *(uint4*)(stage + n * SLD + m8);
        }
    }
}

// ===== pv_mma TRANSPOSED: E^T = vT @ P^T, alpha' computed in prologue ======
// A = g_vT [channel][k] (L2-hot), B = g_sh [token i][k] (read once).
// grid: x = token tile (32), y = channel tile (4), z = batch
__global__ void __launch_bounds__(256, 2)
pv_mma(const float* __restrict__ x, const float* __restrict__ gamma,
       float* __restrict__ out) {
    extern __shared__ char smem[];
    const uint32_t sb  = smem_u32(smem);
    const int tid  = threadIdx.x;
    const int lane = tid & 31, wid = tid >> 5;
    const int wm = (wid & 1) * 64, wn = (wid >> 1) * 32;
    const int i0 = blockIdx.x * 128;      // token tile
    const int c0 = blockIdx.y * 128;      // channel tile
    const int bz = blockIdx.z;

    const __half* Asrc = g_vT + ((size_t)bz * kC + c0) * kHW;
    const __half* Bsrc = g_sh + (size_t)bz * kHW * kHW + (size_t)i0 * kHW;

    const uint32_t sA[2] = {sb, sb + PV_ABUF};
    const uint32_t sB[2] = {sb + 2 * PV_ABUF, sb + 3 * PV_ABUF};
    float* alpha_s = (float*)(smem + 4 * PV_ABUF);   // [128][33] (token rows)

    const int ldrow  = tid >> 3;
    const int ldslot = (tid & 7) * 8;

    // ---- in-prologue alpha': 2 threads per token row, 16 tiles each -------
    {
        const int r = tid >> 1, h = tid & 1;
        const size_t base = ((size_t)bz * kHW + i0 + r) * 32 + h * 16;
        float mt[16], st[16];
        float M2 = -1e30f;
        #pragma unroll
        for (int t = 0; t < 16; t++) {
            mt[t] = g_mt[base + t];
            M2 = fmaxf(M2, mt[t]);
        }
        M2 = fmaxf(M2, __shfl_xor_sync(0xffffffffu, M2, 1));
        float z = 0.f;
        #pragma unroll
        for (int t = 0; t < 16; t++) {
            st[t] = exp2f_fast(mt[t] - M2);         // reuse as alpha-unnorm
            z += g_st[base + t] * st[t];
        }
        z += __shfl_xor_sync(0xffffffffu, z, 1);
        float inv = 1.f / z;
        #pragma unroll
        for (int t = 0; t < 16; t++)
            alpha_s[r * 33 + h * 16 + t] = st[t] * inv;
    }

    float acc[4][4][4];
    #pragma unroll
    for (int i = 0; i < 4; i++)
        #pragma unroll
        for (int j = 0; j < 4; j++)
            #pragma unroll
            for (int r = 0; r < 4; r++) acc[i][j][r] = 0.f;

    const int aRow = wm + (lane & 15);
    const int aCol = (lane >> 4) * 8;
    const int bRow = wn + ((lane >> 4) << 3) + (lane & 7);
    const int bCol = ((lane >> 3) & 1) * 8;

    #pragma unroll
    for (int q = 0; q < 4; q++) {
        int r = q * 32 + ldrow;
        CP16(sA[0] + (r * PV_LDA + ldslot) * 2, Asrc + (size_t)r * kHW + ldslot);
        CP16(sB[0] + (r * PV_LDA + ldslot) * 2, Bsrc + (size_t)r * kHW + ldslot);
    }
    CP_COMMIT();
    __syncthreads();                       // alpha_s ready before mainloop use

    for (int i = 0; i < 64; i++) {
        const int buf = i & 1;
        if (i < 63) {
            const int k0 = (i + 1) * 64;
            #pragma unroll
            for (int q = 0; q < 4; q++) {
                int r = q * 32 + ldrow;
                CP16(sA[buf ^ 1] + (r * PV_LDA + ldslot) * 2,
                     Asrc + (size_t)r * kHW + k0 + ldslot);
                CP16(sB[buf ^ 1] + (r * PV_LDA + ldslot) * 2,
                     Bsrc + (size_t)r * kHW + k0 + ldslot);
            }
            CP_COMMIT();
            CP_WAIT(1);
        } else {
            CP_WAIT(0);
        }
        __syncthreads();

        const int tile = i >> 1;
        __half2 hbv[4];
        #pragma unroll
        for (int nt = 0; nt < 4; nt++) {
            int rn = wn + nt * 8 + (lane >> 2);
            hbv[nt] = __half2half2(__float2half_rn(alpha_s[rn * 33 + tile]));
        }

        #pragma unroll
        for (int ks = 0; ks < 4; ks++) {
            uint32_t af[4][4], bf[4][2];
            #pragma unroll
            for (int mt = 0; mt < 4; mt++)
                ldmx4(af[mt][0], af[mt][1], af[mt][2], af[mt][3],
                      sA[buf] + ((aRow + mt * 16) * PV_LDA + aCol + ks * 16) * 2);
            #pragma unroll
            for (int np = 0; np < 2; np++)
                ldmx4(bf[np * 2][0], bf[np * 2][1], bf[np * 2 + 1][0], bf[np * 2 + 1][1],
                      sB[buf] + ((bRow + np * 16) * PV_LDA + bCol + ks * 16) * 2);
            #pragma unroll
            for (int nt = 0; nt < 4; nt++) {
                *(__half2*)&bf[nt][0] = __hmul2(*(__half2*)&bf[nt][0], hbv[nt]);
                *(__half2*)&bf[nt][1] = __hmul2(*(__half2*)&bf[nt][1], hbv[nt]);
            }
            #pragma unroll
            for (int mt = 0; mt < 4; mt++)
                #pragma unroll
                for (int nt = 0; nt < 4; nt++)
                    mma16816(acc[mt][nt], af[mt], bf[nt]);
        }
        __syncthreads();
    }

    // stage [m=channel][n=token] fp32 -> fused coalesced output
    float* stage = (float*)smem;          // [128][132]
    #pragma unroll
    for (int mt = 0; mt < 4; mt++)
        #pragma unroll
        for (int nt = 0; nt < 4; nt++)
            #pragma unroll
            for (int r = 0; r < 4; r++) {
                int m = wm + mt * 16 + (lane >> 2) + ((r >= 2) ? 8 : 0);
                int n = wn + nt * 8 + (lane & 3) * 2 + (r & 1);
                stage[m * 132 + n] = acc[mt][nt][r];
            }
    __syncthreads();

    const float g = __ldg(gamma);
    const size_t obofs = (size_t)bz * kHW * kC;
    #pragma unroll
    for (int q = 0; q < 16; q++) {
        int idx = tid + q * 256;
        int m   = idx >> 5;
        int n4  = (idx & 31) << 2;
        size_t o = obofs + (size_t)(c0 + m) * kHW + i0 + n4;
        float4 xv = *(const float4*)(x + o);
        const float* sp = stage + m * 132 + n4;
        *(float4*)(out + o) = make_float4(fmaf(g, sp[0], xv.x), fmaf(g, sp[1], xv.y),
                                          fmaf(g, sp[2], xv.z), fmaf(g, sp[3], xv.w));
    }
}

// ---------------------------------------------------------------------------
extern "C" void kernel_launch(void* const* d_in, const int* in_sizes, int n_in,
                              void* d_out, int out_size) {
    const float* x     = (const float*)d_in[0];
    const float* W1    = (const float*)d_in[1];
    const float* W2    = (const float*)d_in[2];
    const float* W3    = (const float*)d_in[3];
    const float* gamma = (const float*)d_in[4];
    float* out = (float*)d_out;

    cudaFuncSetAttribute(pv_mma, cudaFuncAttributeMaxDynamicSharedMemorySize, PV2_SMEM);
    cudaFuncSetAttribute(qkproj_mma, cudaFuncAttributeMaxDynamicSharedMemorySize, PV_SMEM);
    cudaFuncSetAttribute(exp_vproj, cudaFuncAttributeMaxDynamicSharedMemorySize, PV_SMEM);

    prep_all<<<8704, 256>>>(x, W1, W2, W3);               // merged prep
    qkproj_mma<<<dim3(1, 256), 256, PV_SMEM>>>();         // q,k hi/lo (64-row tiles)
    exp_vproj<<<4608, 256, PV_SMEM>>>();                  // exp_tiles || vproj
    pv_mma<<<dim3(32, 4, 4), 256, PV2_SMEM>>>(x, gamma, out);
}

// round 16
// speedup vs baseline: 1.1947x; 1.0254x over previous
#include <cuda_runtime.h>
#include <cuda_fp16.h>
#include <cstdint>

// ---------------------------------------------------------------------------
// PositionAttentionModule: B=4, HW=4096, C=512, Cr=64
//   prep_all             x->hi/lo fp16, W12^T hi/lo, W3^T fp16 (merged)
//   qkproj_mma           3-term split HMMA, 64-row tiles x 256 CTAs
//   exp_vproj            exp_tiles (QK^T + tile softmax -> e fp16) || vproj
//   pv_mma (TRANSPOSED)  E^T = vT @ P^T, alpha' in-prologue + on B-fragments
// R15 change: ONE __syncthreads per pipeline iteration (prefetch moved after
//   the barrier; trailing barrier removed; post-loop barrier added before
//   epilogue smem reuse). Applied to all 4 HMMA mainloops. No numerics change.
// ---------------------------------------------------------------------------

constexpr int kHW  = 4096;
constexpr int kC   = 512;
constexpr int kTok = 4 * kHW;   // 16384

__device__ __half g_qs  [kTok * 128];                   // 4 MB q split [hi|lo]
__device__ __half g_ks  [kTok * 128];                   // 4 MB k split [hi|lo]
__device__ __half g_sh  [(size_t)4 * kHW * kHW];        // 128 MB fp16 e-values
__device__ float  g_mt  [(size_t)kTok * 32];            // 2 MB per-(row,tile) max
__device__ float  g_st  [(size_t)kTok * 32];            // 2 MB per-(row,tile) sum
__device__ __half g_vT  [(size_t)4 * kC * kHW];         // 16 MB vT[b][n][j]
__device__ __half g_xh  [(size_t)kTok * kC];            // 16 MB x hi fp16
__device__ __half g_xl  [(size_t)kTok * kC];            // 16 MB x lo fp16
__device__ __half g_w12h[128 * kC];                     // 128 KB W12^T hi
__device__ __half g_w12l[128 * kC];                     // 128 KB W12^T lo
__device__ __half g_w3T [kC * kC];                      // 512 KB W3^T fp16

// ============================ PTX helpers ==================================
__device__ __forceinline__ uint32_t smem_u32(const void* p) {
    uint32_t a;
    asm("{ .reg .u64 t; cvta.to.shared.u64 t, %1; cvt.u32.u64 %0, t; }"
        : "=r"(a) : "l"(p));
    return a;
}
__device__ __forceinline__ void ldmx4(uint32_t& r0, uint32_t& r1, uint32_t& r2,
                                      uint32_t& r3, uint32_t a) {
    asm volatile("ldmatrix.sync.aligned.m8n8.x4.shared.b16 {%0,%1,%2,%3}, [%4];"
                 : "=r"(r0), "=r"(r1), "=r"(r2), "=r"(r3) : "r"(a));
}
__device__ __forceinline__ void mma16816(float* c, const uint32_t* a,
                                         const uint32_t* b) {
    asm volatile(
        "mma.sync.aligned.m16n8k16.row.col.f32.f16.f16.f32 "
        "{%0,%1,%2,%3}, {%4,%5,%6,%7}, {%8,%9}, {%0,%1,%2,%3};"
        : "+f"(c[0]), "+f"(c[1]), "+f"(c[2]), "+f"(c[3])
        : "r"(a[0]), "r"(a[1]), "r"(a[2]), "r"(a[3]), "r"(b[0]), "r"(b[1]));
}
#define CP16(sm, gp) \
    asm volatile("cp.async.cg.shared.global [%0], [%1], 16;" :: "r"(sm), "l"(gp))
#define CP_COMMIT() asm volatile("cp.async.commit_group;" ::: "memory")
#define CP_WAIT(n)  asm volatile("cp.async.wait_group %0;" :: "n"(n) : "memory")

__device__ __forceinline__ float exp2f_fast(float f) {
    f = fmaxf(f, -126.f);
    float n = floorf(f);
    float r = f - n;
    float p = 1.5252734e-5f;
    p = fmaf(p, r, 1.5403530e-4f);
    p = fmaf(p, r, 1.3333558e-3f);
    p = fmaf(p, r, 9.6181291e-3f);
    p = fmaf(p, r, 5.5504109e-2f);
    p = fmaf(p, r, 2.4022651e-1f);
    p = fmaf(p, r, 6.9314718e-1f);
    p = fmaf(p, r, 1.0f);
    return p * __int_as_float((((int)n) + 127) << 23);
}
constexpr float LOG2E = 1.4426950408889634f;

// ============ HMMA NT skeleton constants ===================================
constexpr int PV_LDA   = 72;                        // halves, padded
constexpr int PV_ABUF  = 128 * PV_LDA * 2;          // 18432 B
constexpr int PV_SMEM  = 4 * PV_ABUF;               // 73728 B
constexpr int PV2_SMEM = PV_SMEM + 128 * 33 * 4;    // + alpha_s = 90624 B

// ================== prep_all: merged elementwise prep ======================
__global__ __launch_bounds__(256) void prep_all(const float* __restrict__ x,
                                                const float* __restrict__ W1,
                                                const float* __restrict__ W2,
                                                const float* __restrict__ W3) {
    __shared__ float t[32][33];
    const int blk = blockIdx.x;
    if (blk < 8192) {
        int idx = blk * 256 + threadIdx.x;
        float4 v = *(const float4*)(x + (size_t)idx * 4);
        __half h0 = __float2half_rn(v.x), h1 = __float2half_rn(v.y);
        __half h2 = __float2half_rn(v.z), h3 = __float2half_rn(v.w);
        __half2* dh = (__half2*)(g_xh + (size_t)idx * 4);
        dh[0] = __halves2half2(h0, h1);
        dh[1] = __halves2half2(h2, h3);
        __half2* dl = (__half2*)(g_xl + (size_t)idx * 4);
        dl[0] = __floats2half2_rn(v.x - __half2float(h0), v.y - __half2float(h1));
        dl[1] = __floats2half2_rn(v.z - __half2float(h2), v.w - __half2float(h3));
    } else if (blk < 8448) {
        int idx = (blk - 8192) * 256 + threadIdx.x;
        int n = idx >> 9, k = idx & 511;
        float v = (n < 64) ? W1[k * 64 + n] : W2[k * 64 + (n - 64)];
        __half hi = __float2half_rn(v);
        __half lo = __float2half_rn(v - __half2float(hi));
        g_w12h[idx] = hi;
        g_w12l[idx] = lo;
    } else {
        int id = blk - 8448;
        const int n0 = (id & 15) * 32;
        const int k0 = (id >> 4) * 32;
        const int tx = threadIdx.x & 31, ty = threadIdx.x >> 5;
        #pragma unroll
        for (int j = 0; j < 4; j++) {
            int kk = ty + j * 8;
            t[kk][tx] = W3[(size_t)(k0 + kk) * kC + n0 + tx];
        }
        __syncthreads();
        #pragma unroll
        for (int j = 0; j < 4; j++) {
            int nn = ty + j * 8;
            g_w3T[(size_t)(n0 + nn) * kC + k0 + tx] = __float2half_rn(t[tx][nn]);
        }
    }
}

// ===== HMMA: q|k projection, 3-term split, 64-row tiles (256 CTAs) =========
__global__ void __launch_bounds__(256, 2) qkproj_mma() {
    extern __shared__ char smem[];
    const uint32_t sb  = smem_u32(smem);
    const int tid  = threadIdx.x;
    const int lane = tid & 31, wid = tid >> 5;
    const int wm = (wid & 1) * 32, wn = (wid >> 1) * 32;
    const int m0 = blockIdx.y * 64;

    const uint32_t sA[2] = {sb, sb + PV_ABUF};
    const uint32_t sB[2] = {sb + 2 * PV_ABUF, sb + 3 * PV_ABUF};

    const int ldrow  = tid >> 3;
    const int ldslot = (tid & 7) * 8;

    float acc[2][4][4];
    #pragma unroll
    for (int i = 0; i < 2; i++)
        #pragma unroll
        for (int j = 0; j < 4; j++)
            #pragma unroll
            for (int r = 0; r < 4; r++) acc[i][j][r] = 0.f;

    const int aRow = wm + (lane & 15);
    const int aCol = (lane >> 4) * 8;
    const int bRow = wn + ((lane >> 4) << 3) + (lane & 7);
    const int bCol = ((lane >> 3) & 1) * 8;

#define QK_PREFETCH(i, buf) do {                                               \
    const int term = (i) >> 3, kc = (i) & 7;                                   \
    const __half* Ap = ((term == 1) ? g_xl : g_xh) + (size_t)m0 * kC + kc * 64; \
    const __half* Bp = ((term == 2) ? g_w12l : g_w12h) + kc * 64;              \
    _Pragma("unroll") for (int q = 0; q < 2; q++) {                            \
        int r = q * 32 + ldrow;                                                \
        CP16(sA[buf] + (r * PV_LDA + ldslot) * 2, Ap + (size_t)r * kC + ldslot); \
    }                                                                          \
    _Pragma("unroll") for (int q = 0; q < 4; q++) {                            \
        int r = q * 32 + ldrow;                                                \
        CP16(sB[buf] + (r * PV_LDA + ldslot) * 2, Bp + (size_t)r * kC + ldslot); \
    }                                                                          \
    CP_COMMIT();                                                               \
} while (0)

    QK_PREFETCH(0, 0);
    for (int i = 0; i < 24; i++) {
        const int buf = i & 1;
        CP_WAIT(0);
        __syncthreads();
        if (i < 23) QK_PREFETCH(i + 1, buf ^ 1);

        #pragma unroll
        for (int ks = 0; ks < 4; ks++) {
            uint32_t af[2][4], bf[4][2];
            #pragma unroll
            for (int mt = 0; mt < 2; mt++)
                ldmx4(af[mt][0], af[mt][1], af[mt][2], af[mt][3],
                      sA[buf] + ((aRow + mt * 16) * PV_LDA + aCol + ks * 16) * 2);
            #pragma unroll
            for (int np = 0; np < 2; np++)
                ldmx4(bf[np * 2][0], bf[np * 2][1], bf[np * 2 + 1][0], bf[np * 2 + 1][1],
                      sB[buf] + ((bRow + np * 16) * PV_LDA + bCol + ks * 16) * 2);
            #pragma unroll
            for (int mt = 0; mt < 2; mt++)
                #pragma unroll
                for (int nt = 0; nt < 4; nt++)
                    mma16816(acc[mt][nt], af[mt], bf[nt]);
        }
    }
#undef QK_PREFETCH
    __syncthreads();                       // tiles free before epilogue reuse

    float* stage = (float*)smem;          // [64][132]
    #pragma unroll
    for (int mt = 0; mt < 2; mt++)
        #pragma unroll
        for (int nt = 0; nt < 4; nt++)
            #pragma unroll
            for (int r = 0; r < 4; r++) {
                int m = wm + mt * 16 + (lane >> 2) + ((r >= 2) ? 8 : 0);
                int n = wn + nt * 8 + (lane & 3) * 2 + (r & 1);
                stage[m * 132 + n] = acc[mt][nt][r];
            }
    __syncthreads();

    #pragma unroll
    for (int q = 0; q < 8; q++) {
        int idx = tid + q * 256;          // 0..2047
        int t   = idx >> 5;               // 0..63
        int c4  = (idx & 31) << 2;
        const float* sp = stage + t * 132 + c4;
        __half hi[4], lo[4];
        #pragma unroll
        for (int j = 0; j < 4; j++) {
            hi[j] = __float2half_rn(sp[j]);
            lo[j] = __float2half_rn(sp[j] - __half2float(hi[j]));
        }
        __half* base = (c4 < 64) ? (g_qs + (size_t)(m0 + t) * 128 + c4)
                                 : (g_ks + (size_t)(m0 + t) * 128 + (c4 - 64));
        *(uint2*)base        = *(uint2*)hi;
        *(uint2*)(base + 64) = *(uint2*)lo;
    }
}

// ======= MERGED: exp_tiles (blocks 0..4095) + vproj (blocks 4096..4607) ====
__global__ void __launch_bounds__(256, 2) exp_vproj() {
    extern __shared__ char smem[];
    const uint32_t sb  = smem_u32(smem);
    const int tid  = threadIdx.x;
    const int lane = tid & 31, wid = tid >> 5;
    const int wm = (wid & 1) * 64, wn = (wid >> 1) * 32;

    const uint32_t sA[2] = {sb, sb + PV_ABUF};
    const uint32_t sB[2] = {sb + 2 * PV_ABUF, sb + 3 * PV_ABUF};
    const int ldrow  = tid >> 3;
    const int ldslot = (tid & 7) * 8;

    const int aRow = wm + (lane & 15);
    const int aCol = (lane >> 4) * 8;
    const int bRow = wn + ((lane >> 4) << 3) + (lane & 7);
    const int bCol = ((lane >> 3) & 1) * 8;

    float acc[4][4][4];
    #pragma unroll
    for (int i = 0; i < 4; i++)
        #pragma unroll
        for (int j = 0; j < 4; j++)
            #pragma unroll
            for (int r = 0; r < 4; r++) acc[i][j][r] = 0.f;

    const int id = blockIdx.x;

    if (id < 4096) {
        const int bz = id >> 10;
        const int m0 = ((id >> 5) & 31) * 128;
        const int n0 = (id & 31) * 128;

        const __half* Asrc = g_qs + ((size_t)bz * kHW + m0) * 128;
        const __half* Bsrc = g_ks + ((size_t)bz * kHW + n0) * 128;

        const int AOFF[3] = {0, 64, 0};
        const int BOFF[3] = {0, 0, 64};

        #pragma unroll
        for (int q = 0; q < 4; q++) {
            int r = q * 32 + ldrow;
            CP16(sA[0] + (r * PV_LDA + ldslot) * 2, Asrc + (size_t)r * 128 + AOFF[0] + ldslot);
            CP16(sB[0] + (r * PV_LDA + ldslot) * 2, Bsrc + (size_t)r * 128 + BOFF[0] + ldslot);
        }
        CP_COMMIT();

        for (int i = 0; i < 3; i++) {
            const int buf = i & 1;
            CP_WAIT(0);
            __syncthreads();
            if (i < 2) {
                #pragma unroll
                for (int q = 0; q < 4; q++) {
                    int r = q * 32 + ldrow;
                    CP16(sA[buf ^ 1] + (r * PV_LDA + ldslot) * 2,
                         Asrc + (size_t)r * 128 + AOFF[i + 1] + ldslot);
                    CP16(sB[buf ^ 1] + (r * PV_LDA + ldslot) * 2,
                         Bsrc + (size_t)r * 128 + BOFF[i + 1] + ldslot);
                }
                CP_COMMIT();
            }

            #pragma unroll
            for (int ks = 0; ks < 4; ks++) {
                uint32_t af[4][4], bf[4][2];
                #pragma unroll
                for (int mt = 0; mt < 4; mt++)
                    ldmx4(af[mt][0], af[mt][1], af[mt][2], af[mt][3],
                          sA[buf] + ((aRow + mt * 16) * PV_LDA + aCol + ks * 16) * 2);
                #pragma unroll
                for (int np = 0; np < 2; np++)
                    ldmx4(bf[np * 2][0], bf[np * 2][1], bf[np * 2 + 1][0], bf[np * 2 + 1][1],
                          sB[buf] + ((bRow + np * 16) * PV_LDA + bCol + ks * 16) * 2);
                #pragma unroll
                for (int mt = 0; mt < 4; mt++)
                    #pragma unroll
                    for (int nt = 0; nt < 4; nt++)
                        mma16816(acc[mt][nt], af[mt], bf[nt]);
            }
        }
        __syncthreads();                   // tiles free before stats smem reuse

        __half* stageh = (__half*)smem;                        // [128][136]
        float*  pmax   = (float*)(smem + 128 * 136 * 2);       // [128][4]
        float*  psum   = (float*)(smem + 128 * 136 * 2 + 2048);// [128][4]
        float*  rowm2  = (float*)(smem + 128 * 136 * 2 + 4096);// [128]
        const int cg = wid >> 1;

        #pragma unroll
        for (int mt = 0; mt < 4; mt++) {
            float ma = -1e30f, mb = -1e30f;
            #pragma unroll
            for (int nt = 0; nt < 4; nt++) {
                ma = fmaxf(ma, fmaxf(acc[mt][nt][0], acc[mt][nt][1]));
                mb = fmaxf(mb, fmaxf(acc[mt][nt][2], acc[mt][nt][3]));
            }
            ma = fmaxf(ma, __shfl_xor_sync(0xffffffffu, ma, 1));
            ma = fmaxf(ma, __shfl_xor_sync(0xffffffffu, ma, 2));
            mb = fmaxf(mb, __shfl_xor_sync(0xffffffffu, mb, 1));
            mb = fmaxf(mb, __shfl_xor_sync(0xffffffffu, mb, 2));
            if ((lane & 3) == 0) {
                int ra = wm + mt * 16 + (lane >> 2);
                pmax[ra * 4 + cg]       = ma;
                pmax[(ra + 8) * 4 + cg] = mb;
            }
        }
        __syncthreads();
        if (tid < 128) {
            float m = fmaxf(fmaxf(pmax[tid * 4], pmax[tid * 4 + 1]),
                            fmaxf(pmax[tid * 4 + 2], pmax[tid * 4 + 3]));
            rowm2[tid] = m * LOG2E;
        }
        __syncthreads();

        #pragma unroll
        for (int mt = 0; mt < 4; mt++) {
            int ra = wm + mt * 16 + (lane >> 2);
            float m2a = rowm2[ra], m2b = rowm2[ra + 8];
            float sa = 0.f, sb2 = 0.f;
            #pragma unroll
            for (int nt = 0; nt < 4; nt++) {
                int col = wn + nt * 8 + (lane & 3) * 2;
                float e0 = exp2f_fast(fmaf(acc[mt][nt][0], LOG2E, -m2a));
                float e1 = exp2f_fast(fmaf(acc[mt][nt][1], LOG2E, -m2a));
                float e2 = exp2f_fast(fmaf(acc[mt][nt][2], LOG2E, -m2b));
                float e3 = exp2f_fast(fmaf(acc[mt][nt][3], LOG2E, -m2b));
                sa  += e0 + e1;
                sb2 += e2 + e3;
                *(__half2*)(stageh + ra * 136 + col)       = __floats2half2_rn(e0, e1);
                *(__half2*)(stageh + (ra + 8) * 136 + col) = __floats2half2_rn(e2, e3);
            }
            sa  += __shfl_xor_sync(0xffffffffu, sa, 1);
            sa  += __shfl_xor_sync(0xffffffffu, sa, 2);
            sb2 += __shfl_xor_sync(0xffffffffu, sb2, 1);
            sb2 += __shfl_xor_sync(0xffffffffu, sb2, 2);
            if ((lane & 3) == 0) {
                psum[ra * 4 + cg]       = sa;
                psum[(ra + 8) * 4 + cg] = sb2;
            }
        }
        __syncthreads();

        if (tid < 128) {
            float s = psum[tid * 4] + psum[tid * 4 + 1] + psum[tid * 4 + 2] + psum[tid * 4 + 3];
            size_t ridx = ((size_t)bz * kHW + m0 + tid) * 32 + (n0 >> 7);
            g_mt[ridx] = rowm2[tid];
            g_st[ridx] = s;
        }

        __half* Pp = g_sh + (size_t)bz * kHW * kHW;
        #pragma unroll
        for (int q = 0; q < 8; q++) {
            int idx = tid + q * 256;
            int r = idx >> 4, c = (idx & 15) * 8;
            *(uint4*)(Pp + (size_t)(m0 + r) * kHW + n0 + c) = *(uint4*)(stageh + r * 136 + c);
        }
    } else {
        const int id2 = id - 4096;
        const int n0 = (id2 & 3) * 128;
        const int m0 = (id2 >> 2) * 128;

        const __half* Asrc = g_xh + (size_t)m0 * kC;
        const __half* Bsrc = g_w3T + (size_t)n0 * kC;

        #pragma unroll
        for (int q = 0; q < 4; q++) {
            int r = q * 32 + ldrow;
            CP16(sA[0] + (r * PV_LDA + ldslot) * 2, Asrc + (size_t)r * kC + ldslot);
            CP16(sB[0] + (r * PV_LDA + ldslot) * 2, Bsrc + (size_t)r * kC + ldslot);
        }
        CP_COMMIT();

        for (int i = 0; i < 8; i++) {
            const int buf = i & 1;
            CP_WAIT(0);
            __syncthreads();
            if (i < 7) {
                const int k0 = (i + 1) * 64;
                #pragma unroll
                for (int q = 0; q < 4; q++) {
                    int r = q * 32 + ldrow;
                    CP16(sA[buf ^ 1] + (r * PV_LDA + ldslot) * 2,
                         Asrc + (size_t)r * kC + k0 + ldslot);
                    CP16(sB[buf ^ 1] + (r * PV_LDA + ldslot) * 2,
                         Bsrc + (size_t)r * kC + k0 + ldslot);
                }
                CP_COMMIT();
            }

            #pragma unroll
            for (int ks = 0; ks < 4; ks++) {
                uint32_t af[4][4], bf[4][2];
                #pragma unroll
                for (int mt = 0; mt < 4; mt++)
                    ldmx4(af[mt][0], af[mt][1], af[mt][2], af[mt][3],
                          sA[buf] + ((aRow + mt * 16) * PV_LDA + aCol + ks * 16) * 2);
                #pragma unroll
                for (int np = 0; np < 2; np++)
                    ldmx4(bf[np * 2][0], bf[np * 2][1], bf[np * 2 + 1][0], bf[np * 2 + 1][1],
                          sB[buf] + ((bRow + np * 16) * PV_LDA + bCol + ks * 16) * 2);
                #pragma unroll
                for (int mt = 0; mt < 4; mt++)
                    #pragma unroll
                    for (int nt = 0; nt < 4; nt++)
                        mma16816(acc[mt][nt], af[mt], bf[nt]);
            }
        }
        __syncthreads();                   // tiles free before epilogue reuse

        __half* stage = (__half*)smem;        // [128][136]
        constexpr int SLD = 136;
        #pragma unroll
        for (int mt = 0; mt < 4; mt++)
            #pragma unroll
            for (int nt = 0; nt < 4; nt++)
                #pragma unroll
                for (int r = 0; r < 4; r++) {
                    int m = wm + mt * 16 + (lane >> 2) + ((r >= 2) ? 8 : 0);
                    int n = wn + nt * 8 + (lane & 3) * 2 + (r & 1);
                    stage[n * SLD + m] = __float2half_rn(acc[mt][nt][r]);
                }
        __syncthreads();

        const int bz = m0 >> 12;
        const int ml = m0 & 4095;
        #pragma unroll
        for (int q = 0; q < 8; q++) {
            int idx = tid + q * 256;
            int n   = idx >> 4;
            int m8  = (idx & 15) << 3;
            __half* dst = g_vT + ((size_t)bz * kC + n0 + n) * kHW + ml + m8;
            *(uint4*)dst = *(uint4*)(stage + n * SLD + m8);
        }
    }
}

// ===== pv_mma TRANSPOSED: E^T = vT @ P^T, alpha' in prologue ===============
// A = g_vT [channel][k] (L2-hot), B = g_sh [token i][k] (read once).
// grid: x = token tile (32), y = channel tile (4), z = batch
__global__ void __launch_bounds__(256, 2)
pv_mma(const float* __restrict__ x, const float* __restrict__ gamma,
       float* __restrict__ out) {
    extern __shared__ char smem[];
    const uint32_t sb  = smem_u32(smem);
    const int tid  = threadIdx.x;
    const int lane = tid & 31, wid = tid >> 5;
    const int wm = (wid & 1) * 64, wn = (wid >> 1) * 32;
    const int i0 = blockIdx.x * 128;      // token tile
    const int c0 = blockIdx.y * 128;      // channel tile
    const int bz = blockIdx.z;

    const __half* Asrc = g_vT + ((size_t)bz * kC + c0) * kHW;
    const __half* Bsrc = g_sh + (size_t)bz * kHW * kHW + (size_t)i0 * kHW;

    const uint32_t sA[2] = {sb, sb + PV_ABUF};
    const uint32_t sB[2] = {sb + 2 * PV_ABUF, sb + 3 * PV_ABUF};
    float* alpha_s = (float*)(smem + 4 * PV_ABUF);   // [128][33] (token rows)

    const int ldrow  = tid >> 3;
    const int ldslot = (tid & 7) * 8;

    // prologue prefetch stage 0
    #pragma unroll
    for (int q = 0; q < 4; q++) {
        int r = q * 32 + ldrow;
        CP16(sA[0] + (r * PV_LDA + ldslot) * 2, Asrc + (size_t)r * kHW + ldslot);
        CP16(sB[0] + (r * PV_LDA + ldslot) * 2, Bsrc + (size_t)r * kHW + ldslot);
    }
    CP_COMMIT();

    // ---- in-prologue alpha': 2 threads per token row, 16 tiles each -------
    {
        const int r = tid >> 1, h = tid & 1;
        const size_t base = ((size_t)bz * kHW + i0 + r) * 32 + h * 16;
        float mt[16], st[16];
        float M2 = -1e30f;
        #pragma unroll
        for (int t = 0; t < 16; t++) {
            mt[t] = g_mt[base + t];
            M2 = fmaxf(M2, mt[t]);
        }
        M2 = fmaxf(M2, __shfl_xor_sync(0xffffffffu, M2, 1));
        float z = 0.f;
        #pragma unroll
        for (int t = 0; t < 16; t++) {
            st[t] = exp2f_fast(mt[t] - M2);
            z += g_st[base + t] * st[t];
        }
        z += __shfl_xor_sync(0xffffffffu, z, 1);
        float inv = 1.f / z;
        #pragma unroll
        for (int t = 0; t < 16; t++)
            alpha_s[r * 33 + h * 16 + t] = st[t] * inv;
    }

    float acc[4][4][4];
    #pragma unroll
    for (int i = 0; i < 4; i++)
        #pragma unroll
        for (int j = 0; j < 4; j++)
            #pragma unroll
            for (int r = 0; r < 4; r++) acc[i][j][r] = 0.f;

    const int aRow = wm + (lane & 15);
    const int aCol = (lane >> 4) * 8;
    const int bRow = wn + ((lane >> 4) << 3) + (lane & 7);
    const int bCol = ((lane >> 3) & 1) * 8;

    for (int i = 0; i < 64; i++) {
        const int buf = i & 1;
        CP_WAIT(0);
        __syncthreads();                  // data visible; prev compute done; alpha ready
        if (i < 63) {
            const int k0 = (i + 1) * 64;
            #pragma unroll
            for (int q = 0; q < 4; q++) {
                int r = q * 32 + ldrow;
                CP16(sA[buf ^ 1] + (r * PV_LDA + ldslot) * 2,
                     Asrc + (size_t)r * kHW + k0 + ldslot);
                CP16(sB[buf ^ 1] + (r * PV_LDA + ldslot) * 2,
                     Bsrc + (size_t)r * kHW + k0 + ldslot);
            }
            CP_COMMIT();
        }

        const int tile = i >> 1;
        __half2 hbv[4];
        #pragma unroll
        for (int nt = 0; nt < 4; nt++) {
            int rn = wn + nt * 8 + (lane >> 2);
            hbv[nt] = __half2half2(__float2half_rn(alpha_s[rn * 33 + tile]));
        }

        #pragma unroll
        for (int ks = 0; ks < 4; ks++) {
            uint32_t af[4][4], bf[4][2];
            #pragma unroll
            for (int mt = 0; mt < 4; mt++)
                ldmx4(af[mt][0], af[mt][1], af[mt][2], af[mt][3],
                      sA[buf] + ((aRow + mt * 16) * PV_LDA + aCol + ks * 16) * 2);
            #pragma unroll
            for (int np = 0; np < 2; np++)
                ldmx4(bf[np * 2][0], bf[np * 2][1], bf[np * 2 + 1][0], bf[np * 2 + 1][1],
                      sB[buf] + ((bRow + np * 16) * PV_LDA + bCol + ks * 16) * 2);
            #pragma unroll
            for (int nt = 0; nt < 4; nt++) {
                *(__half2*)&bf[nt][0] = __hmul2(*(__half2*)&bf[nt][0], hbv[nt]);
                *(__half2*)&bf[nt][1] = __hmul2(*(__half2*)&bf[nt][1], hbv[nt]);
            }
            #pragma unroll
            for (int mt = 0; mt < 4; mt++)
                #pragma unroll
                for (int nt = 0; nt < 4; nt++)
                    mma16816(acc[mt][nt], af[mt], bf[nt]);
        }
    }
    __syncthreads();                       // tiles free before epilogue reuse

    // stage [m=channel][n=token] fp32 -> fused coalesced output
    float* stage = (float*)smem;          // [128][132]
    #pragma unroll
    for (int mt = 0; mt < 4; mt++)
        #pragma unroll
        for (int nt = 0; nt < 4; nt++)
            #pragma unroll
            for (int r = 0; r < 4; r++) {
                int m = wm + mt * 16 + (lane >> 2) + ((r >= 2) ? 8 : 0);
                int n = wn + nt * 8 + (lane & 3) * 2 + (r & 1);
                stage[m * 132 + n] = acc[mt][nt][r];
            }
    __syncthreads();

    const float g = __ldg(gamma);
    const size_t obofs = (size_t)bz * kHW * kC;
    #pragma unroll
    for (int q = 0; q < 16; q++) {
        int idx = tid + q * 256;
        int m   = idx >> 5;
        int n4  = (idx & 31) << 2;
        size_t o = obofs + (size_t)(c0 + m) * kHW + i0 + n4;
        float4 xv = *(const float4*)(x + o);
        const float* sp = stage + m * 132 + n4;
        *(float4*)(out + o) = make_float4(fmaf(g, sp[0], xv.x), fmaf(g, sp[1], xv.y),
                                          fmaf(g, sp[2], xv.z), fmaf(g, sp[3], xv.w));
    }
}

// ---------------------------------------------------------------------------
extern "C" void kernel_launch(void* const* d_in, const int* in_sizes, int n_in,
                              void* d_out, int out_size) {
    const float* x     = (const float*)d_in[0];
    const float* W1    = (const float*)d_in[1];
    const float* W2    = (const float*)d_in[2];
    const float* W3    = (const float*)d_in[3];
    const float* gamma = (const float*)d_in[4];
    float* out = (float*)d_out;

    cudaFuncSetAttribute(pv_mma, cudaFuncAttributeMaxDynamicSharedMemorySize, PV2_SMEM);
    cudaFuncSetAttribute(qkproj_mma, cudaFuncAttributeMaxDynamicSharedMemorySize, PV_SMEM);
    cudaFuncSetAttribute(exp_vproj, cudaFuncAttributeMaxDynamicSharedMemorySize, PV_SMEM);

    prep_all<<<8704, 256>>>(x, W1, W2, W3);               // merged prep
    qkproj_mma<<<dim3(1, 256), 256, PV_SMEM>>>();         // q,k hi/lo (64-row tiles)
    exp_vproj<<<4608, 256, PV_SMEM>>>();                  // exp_tiles || vproj
    pv_mma<<<dim3(32, 4, 4), 256, PV2_SMEM>>>(x, gamma, out);
}